// round 10
// baseline (speedup 1.0000x reference)
#include <cuda_runtime.h>
#include <cuda_fp16.h>
#include <cstdint>

#define N_NODES 50000
#define N_EDGES 800000
#define HID 64
#define HEADS 4
#define CDIM 64
#define HC 256   // HEADS*CDIM
#define L_LAYERS 2
#define NEG_SLOPE 0.2f
#define LN_EPS 1e-5f
#define SCAN_BLK 1024
#define N_SCAN_BLOCKS ((N_NODES + SCAN_BLK - 1) / SCAN_BLK)   // 49

// ---------------- device scratch (no allocations allowed) ----------------
__device__ __half g_xh[(size_t)N_NODES * HC];     // projected nodes, fp16 [N,256]
__device__ float g_as[N_NODES * HEADS];           // alpha_src [N,4]
__device__ float g_ad[N_NODES * HEADS];           // alpha_dst [N,4]
__device__ float g_exs[(size_t)N_EDGES * HEADS];  // exp(alpha), CSR order [E,4]
__device__ float g_ea_csr[(size_t)N_EDGES * 4];   // edge_attr in CSR order [E,4]
__device__ float g_z[(size_t)N_NODES * HID];      // inter-layer activations
__device__ int   g_src[N_EDGES];
__device__ int   g_dst[N_EDGES];
__device__ int   g_rank[N_EDGES];                 // rank of edge within its dst bucket
__device__ int   g_csr_src[N_EDGES];              // src id per CSR slot
__device__ int   g_rowptr[N_NODES + 1];
__device__ int   g_deg[N_NODES];
__device__ int   g_bsum[N_SCAN_BLOCKS];
__device__ int   g_boff[N_SCAN_BLOCKS];
__device__ float g_M2[2 * 12];                    // edge-attr dual matrices, both layers
__device__ int   g_is64;

// ---------------- K0a: detect dtype + zero degrees (fused) ----------------
__global__ void k_detect_zero(const int* __restrict__ ei32) {
    const int i = blockIdx.x * blockDim.x + threadIdx.x;
    if (i < N_NODES) g_deg[i] = 0;
    if (i == 0) {
        int zeros = 0;
        for (int k = 1; k < 256; k += 2) if (ei32[k] == 0) zeros++;
        g_is64 = (zeros > 100) ? 1 : 0;   // int64 data: high words all zero
    }
}

// ---------------- K0b: normalize edge index + count degrees + capture rank ----------------
__global__ void k_convert(const void* __restrict__ ei) {
    const int e = blockIdx.x * blockDim.x + threadIdx.x;
    if (e >= N_EDGES) return;
    int s, d;
    if (g_is64) {
        const long long* p = (const long long*)ei;
        s = (int)p[e]; d = (int)p[N_EDGES + e];
    } else {
        const int* p = (const int*)ei;
        s = p[e]; d = p[N_EDGES + e];
    }
    g_src[e] = s;
    g_dst[e] = d;
    g_rank[e] = atomicAdd(&g_deg[d], 1);
}

// ---------------- K0c: scan phase A — per-block exclusive scan ----------------
__global__ void __launch_bounds__(SCAN_BLK) k_scanA() {
    __shared__ int warp_sums[32];
    const int tid = threadIdx.x;
    const int i = blockIdx.x * SCAN_BLK + tid;
    const int v = (i < N_NODES) ? g_deg[i] : 0;
    int x = v;
#pragma unroll
    for (int o = 1; o < 32; o <<= 1) {
        int y = __shfl_up_sync(0xffffffffu, x, o);
        if ((tid & 31) >= o) x += y;
    }
    if ((tid & 31) == 31) warp_sums[tid >> 5] = x;
    __syncthreads();
    if (tid < 32) {
        int w = warp_sums[tid];
#pragma unroll
        for (int o = 1; o < 32; o <<= 1) {
            int y = __shfl_up_sync(0xffffffffu, w, o);
            if (tid >= o) w += y;
        }
        warp_sums[tid] = w;
    }
    __syncthreads();
    const int excl = x - v + ((tid >= 32) ? warp_sums[(tid >> 5) - 1] : 0);
    if (i < N_NODES) g_rowptr[i] = excl;
    if (tid == SCAN_BLK - 1) g_bsum[blockIdx.x] = excl + v;
}

// ---------------- K0d: scan phase B — scan the 49 block sums ----------------
__global__ void k_scanB() {
    __shared__ int s0;
    const int tid = threadIdx.x;   // 64 threads
    const int v = (tid < N_SCAN_BLOCKS) ? g_bsum[tid] : 0;
    int x = v;
#pragma unroll
    for (int o = 1; o < 32; o <<= 1) {
        int y = __shfl_up_sync(0xffffffffu, x, o);
        if ((tid & 31) >= o) x += y;
    }
    if (tid == 31) s0 = x;
    __syncthreads();
    if (tid >= 32) x += s0;
    if (tid < N_SCAN_BLOCKS) g_boff[tid] = x - v;
    if (tid == N_SCAN_BLOCKS - 1) g_rowptr[N_NODES] = x;
}

// ---------------- K0e: scan phase C — add block offsets ----------------
__global__ void __launch_bounds__(SCAN_BLK) k_scanC() {
    const int i = blockIdx.x * SCAN_BLK + threadIdx.x;
    if (i < N_NODES) g_rowptr[i] += g_boff[blockIdx.x];
}

// ---------------- K0f: fill CSR (no atomics: pos = rowptr[dst] + rank) ----------------
__global__ void k_fill(const float* __restrict__ ea) {
    const int e = blockIdx.x * blockDim.x + threadIdx.x;
    if (e >= N_EDGES) return;
    const int pos = g_rowptr[g_dst[e]] + g_rank[e];
    g_csr_src[pos] = g_src[e];
    const float* p = ea + (size_t)e * 3;
    ((float4*)g_ea_csr)[pos] = make_float4(p[0], p[1], p[2], 0.f);
}

// ---------------- K0g: M[l][d][h] for BOTH layers in one launch ----------------
__global__ void k_M_both(const float* __restrict__ We, const float* __restrict__ a_e) {
    const int t = threadIdx.x;
    if (t < 24) {
        const int l = t / 12, r = t % 12;
        const int d = r >> 2, h = r & 3;
        const float* Wel = We + (size_t)l * 3 * HC;
        const float* ael = a_e + (size_t)l * HC;
        float s = 0.f;
        for (int c = 0; c < CDIM; c++)
            s += Wel[d * HC + h * CDIM + c] * ael[h * CDIM + c];
        g_M2[t] = s;   // layout g_M2[l*12 + d*4 + h]
    }
}

// ---------------- K1: node projection (fp16 out) + alpha_src/alpha_dst ----------------
#define NB 8
__global__ void __launch_bounds__(256) k_node_proj(
    const float* __restrict__ z, const float* __restrict__ W,
    const float* __restrict__ a_s, const float* __restrict__ a_d)
{
    extern __shared__ float smem[];
    float* Wsh  = smem;                 // 64*256 = 16384 floats
    float* zshT = smem + 16384;         // [k][nb] transposed, 512 floats
    float* reds = smem + 16896;         // 64 floats
    float* redd = smem + 16960;         // 64 floats

    const int tid = threadIdx.x;
    for (int i = tid; i < (HID * HC) / 4; i += 256)
        ((float4*)Wsh)[i] = ((const float4*)W)[i];
    const float as = a_s[tid];
    const float ad = a_d[tid];
    __syncthreads();

    const int lane = tid & 31;
    const int wid = tid >> 5;
    const int nblocks = gridDim.x;

    for (int g = blockIdx.x; g * NB < N_NODES; g += nblocks) {
        const int n0 = g * NB;
        for (int i = tid; i < NB * HID; i += 256) {
            const int nb = i >> 6, k = i & 63;
            zshT[k * NB + nb] = z[(size_t)n0 * HID + i];
        }
        __syncthreads();

        float acc[NB];
#pragma unroll
        for (int nb = 0; nb < NB; nb++) acc[nb] = 0.f;

#pragma unroll
        for (int k = 0; k < HID; k++) {
            const float w = Wsh[k * HC + tid];
            const float4 za = ((float4*)zshT)[k * 2];
            const float4 zb = ((float4*)zshT)[k * 2 + 1];
            acc[0] = fmaf(za.x, w, acc[0]);
            acc[1] = fmaf(za.y, w, acc[1]);
            acc[2] = fmaf(za.z, w, acc[2]);
            acc[3] = fmaf(za.w, w, acc[3]);
            acc[4] = fmaf(zb.x, w, acc[4]);
            acc[5] = fmaf(zb.y, w, acc[5]);
            acc[6] = fmaf(zb.z, w, acc[6]);
            acc[7] = fmaf(zb.w, w, acc[7]);
        }

#pragma unroll
        for (int nb = 0; nb < NB; nb++)
            g_xh[(size_t)(n0 + nb) * HC + tid] = __float2half(acc[nb]);

        // alpha reductions use the fp32 accumulators (no fp16 error here)
#pragma unroll
        for (int nb = 0; nb < NB; nb++) {
            float ps = acc[nb] * as;
            float pd = acc[nb] * ad;
#pragma unroll
            for (int o = 16; o; o >>= 1) {
                ps += __shfl_down_sync(0xffffffffu, ps, o);
                pd += __shfl_down_sync(0xffffffffu, pd, o);
            }
            if (lane == 0) { reds[nb * 8 + wid] = ps; redd[nb * 8 + wid] = pd; }
        }
        __syncthreads();
        if (tid < 32) {
            const int nb = tid >> 2, h = tid & 3;
            g_as[(n0 + nb) * HEADS + h] = reds[nb * 8 + 2 * h] + reds[nb * 8 + 2 * h + 1];
            g_ad[(n0 + nb) * HEADS + h] = redd[nb * 8 + 2 * h] + redd[nb * 8 + 2 * h + 1];
        }
        __syncthreads();
    }
}

// ---------------- K2: fused alpha + CSR message pass + finalize ----------------
// ONE WARP per dst node. Sweep 1: 32-wide edge parallelism. Sweep 2: two
// 16-lane halves process edges j (lanes 0-15) and j+1 (lanes 16-31) in
// flight, with software-pipelined prefetch of the next indices.
__global__ void __launch_bounds__(256) k_gat_msg(
    int layer, float* __restrict__ zout, const float* __restrict__ bias,
    const float* __restrict__ gamma, const float* __restrict__ beta)
{
    const int t = threadIdx.x;
    const int lane = t & 31;
    const int half = lane >> 4;          // which edge of the pair
    const int q = lane & 15;             // position within the 16-lane half
    const int n = blockIdx.x * 8 + (t >> 5);
    const int row0 = g_rowptr[n];
    const int row1 = g_rowptr[n + 1];

    const float* M = g_M2 + layer * 12;
    const float4 ad4 = *(const float4*)(g_ad + n * 4);
    const float M0 = M[0], M1 = M[1], M2_ = M[2],  M3  = M[3];
    const float M4 = M[4], M5 = M[5], M6  = M[6],  M7  = M[7];
    const float M8 = M[8], M9 = M[9], M10 = M[10], M11 = M[11];

    // sweep 1: alpha -> exp per edge (32-lane strided), denom accumulation,
    // coalesced store of ex into CSR order.
    float4 dn = make_float4(0.f, 0.f, 0.f, 0.f);
    for (int j = row0 + lane; j < row1; j += 32) {
        const int s = g_csr_src[j];
        const float4 as4 = *(const float4*)(g_as + s * 4);
        const float4 ea4 = ((const float4*)g_ea_csr)[j];
        float a0 = as4.x + ad4.x + ea4.x * M0  + ea4.y * M4 + ea4.z * M8;
        float a1 = as4.y + ad4.y + ea4.x * M1  + ea4.y * M5 + ea4.z * M9;
        float a2 = as4.z + ad4.z + ea4.x * M2_ + ea4.y * M6 + ea4.z * M10;
        float a3 = as4.w + ad4.w + ea4.x * M3  + ea4.y * M7 + ea4.z * M11;
        a0 = (a0 < 0.f) ? NEG_SLOPE * a0 : a0;
        a1 = (a1 < 0.f) ? NEG_SLOPE * a1 : a1;
        a2 = (a2 < 0.f) ? NEG_SLOPE * a2 : a2;
        a3 = (a3 < 0.f) ? NEG_SLOPE * a3 : a3;
        // softmax shift-invariance + alpha ~ O(10): segment-max pass skipped.
        const float4 ex = make_float4(__expf(a0), __expf(a1), __expf(a2), __expf(a3));
        ((float4*)g_exs)[j] = ex;
        dn.x += ex.x; dn.y += ex.y; dn.z += ex.z; dn.w += ex.w;
    }
#pragma unroll
    for (int o = 16; o; o >>= 1) {
        dn.x += __shfl_xor_sync(0xffffffffu, dn.x, o);
        dn.y += __shfl_xor_sync(0xffffffffu, dn.y, o);
        dn.z += __shfl_xor_sync(0xffffffffu, dn.z, o);
        dn.w += __shfl_xor_sync(0xffffffffu, dn.w, o);
    }
    const float i0 = __frcp_rn(dn.x + 1e-16f);
    const float i1 = __frcp_rn(dn.y + 1e-16f);
    const float i2 = __frcp_rn(dn.z + 1e-16f);
    const float i3 = __frcp_rn(dn.w + 1e-16f);
    __syncwarp();   // order g_exs stores before cross-lane readback

    // sweep 2: each 16-lane half walks edges {row0+half, +2, ...} with
    // next-iteration prefetch. Lane q owns channels 8*(q&7)..+7.
    float accA[8], accB[8];
#pragma unroll
    for (int i = 0; i < 8; i++) { accA[i] = 0.f; accB[i] = 0.f; }

    int j = row0 + half;
    if (j < row1) {
        int s = g_csr_src[j];
        float4 ex = ((const float4*)g_exs)[j];
        while (true) {
            const int jn = j + 2;
            const bool more = jn < row1;
            int sn = 0;
            float4 exn = make_float4(0.f, 0.f, 0.f, 0.f);
            if (more) {                       // prefetch next edge's metadata
                sn = g_csr_src[jn];
                exn = ((const float4*)g_exs)[jn];
            }
            const float cA = (q < 8) ? (ex.x * i0) : (ex.y * i1);
            const float cB = (q < 8) ? (ex.z * i2) : (ex.w * i3);
            const __half* xr = g_xh + (size_t)s * HC;
            const uint4 hA = *(const uint4*)(xr + 8 * q);          // heads 0|1
            const uint4 hB = *(const uint4*)(xr + 128 + 8 * q);    // heads 2|3
            const float2 a0 = __half22float2(*(const __half2*)&hA.x);
            const float2 a1 = __half22float2(*(const __half2*)&hA.y);
            const float2 a2 = __half22float2(*(const __half2*)&hA.z);
            const float2 a3 = __half22float2(*(const __half2*)&hA.w);
            const float2 b0 = __half22float2(*(const __half2*)&hB.x);
            const float2 b1 = __half22float2(*(const __half2*)&hB.y);
            const float2 b2 = __half22float2(*(const __half2*)&hB.z);
            const float2 b3 = __half22float2(*(const __half2*)&hB.w);
            accA[0] = fmaf(cA, a0.x, accA[0]); accA[1] = fmaf(cA, a0.y, accA[1]);
            accA[2] = fmaf(cA, a1.x, accA[2]); accA[3] = fmaf(cA, a1.y, accA[3]);
            accA[4] = fmaf(cA, a2.x, accA[4]); accA[5] = fmaf(cA, a2.y, accA[5]);
            accA[6] = fmaf(cA, a3.x, accA[6]); accA[7] = fmaf(cA, a3.y, accA[7]);
            accB[0] = fmaf(cB, b0.x, accB[0]); accB[1] = fmaf(cB, b0.y, accB[1]);
            accB[2] = fmaf(cB, b1.x, accB[2]); accB[3] = fmaf(cB, b1.y, accB[3]);
            accB[4] = fmaf(cB, b2.x, accB[4]); accB[5] = fmaf(cB, b2.y, accB[5]);
            accB[6] = fmaf(cB, b3.x, accB[6]); accB[7] = fmaf(cB, b3.y, accB[7]);
            if (!more) break;
            j = jn; s = sn; ex = exn;
        }
    }

    // combine: head-halves (xor 8), then the two edge-halves (xor 16)
    float tot[8];
#pragma unroll
    for (int i = 0; i < 8; i++) {
        float v = accA[i] + accB[i];
        v += __shfl_xor_sync(0xffffffffu, v, 8);
        v += __shfl_xor_sync(0xffffffffu, v, 16);
        tot[i] = v;   // lane holds full 4-head sum for c = 8*(lane&7)+i
    }

    // finalize: head-mean + bias + LN + SiLU (values mirrored across 8-lane groups)
    const int c0i = 8 * (lane & 7);
    float v[8];
    float s = 0.f;
#pragma unroll
    for (int i = 0; i < 8; i++) {
        v[i] = 0.25f * tot[i] + bias[c0i + i];
        s += v[i];
    }
#pragma unroll
    for (int o = 4; o; o >>= 1) s += __shfl_xor_sync(0xffffffffu, s, o);
    const float mu = s * (1.f / 64.f);
    float qs = 0.f;
#pragma unroll
    for (int i = 0; i < 8; i++) {
        v[i] -= mu;
        qs += v[i] * v[i];
    }
#pragma unroll
    for (int o = 4; o; o >>= 1) qs += __shfl_xor_sync(0xffffffffu, qs, o);
    const float rs = rsqrtf(qs * (1.f / 64.f) + LN_EPS);

    if (lane < 8) {
        float y[8];
#pragma unroll
        for (int i = 0; i < 8; i++) {
            const float tv = v[i] * rs * gamma[c0i + i] + beta[c0i + i];
            y[i] = tv / (1.f + __expf(-tv));
        }
        float4* dst = (float4*)(zout + (size_t)n * HID + c0i);
        dst[0] = make_float4(y[0], y[1], y[2], y[3]);
        dst[1] = make_float4(y[4], y[5], y[6], y[7]);
    }
}

// ---------------- launcher ----------------
extern "C" void kernel_launch(void* const* d_in, const int* in_sizes, int n_in,
                              void* d_out, int out_size) {
    (void)in_sizes; (void)n_in; (void)out_size;
    const float* h     = (const float*)d_in[1];
    const void*  ei    = d_in[2];
    const float* ea    = (const float*)d_in[3];
    const float* W     = (const float*)d_in[4];
    const float* We    = (const float*)d_in[5];
    const float* as_   = (const float*)d_in[6];
    const float* ad_   = (const float*)d_in[7];
    const float* ae_   = (const float*)d_in[8];
    const float* bias  = (const float*)d_in[9];
    const float* gamma = (const float*)d_in[10];
    const float* beta  = (const float*)d_in[11];
    float* out = (float*)d_out;

    const int smem_bytes = 17024 * 4;   // 68096 B
    cudaFuncSetAttribute(k_node_proj, cudaFuncAttributeMaxDynamicSharedMemorySize, smem_bytes);

    float* zbuf = nullptr;
    cudaGetSymbolAddress((void**)&zbuf, g_z);

    // ---- preamble: CSR build + both layers' M (all layer-invariant) ----
    k_detect_zero<<<(N_NODES + 255) / 256, 256>>>((const int*)ei);
    k_convert<<<(N_EDGES + 255) / 256, 256>>>(ei);
    k_scanA<<<N_SCAN_BLOCKS, SCAN_BLK>>>();
    k_scanB<<<1, 64>>>();
    k_scanC<<<N_SCAN_BLOCKS, SCAN_BLK>>>();
    k_fill<<<(N_EDGES + 255) / 256, 256>>>(ea);
    k_M_both<<<1, 32>>>(We, ae_);

    const float* zin = h;
    for (int l = 0; l < L_LAYERS; l++) {
        k_node_proj<<<444, 256, smem_bytes>>>(zin, W + (size_t)l * HID * HC,
                                              as_ + (size_t)l * HC, ad_ + (size_t)l * HC);
        k_gat_msg<<<N_NODES / 8, 256>>>(l, l == 0 ? zbuf : out,
                                        bias + (size_t)l * HID,
                                        gamma + (size_t)l * HID,
                                        beta + (size_t)l * HID);
        zin = zbuf;
    }
}

// round 11
// speedup vs baseline: 1.0129x; 1.0129x over previous
#include <cuda_runtime.h>
#include <cuda_fp16.h>
#include <cstdint>

#define N_NODES 50000
#define N_EDGES 800000
#define HID 64
#define HEADS 4
#define CDIM 64
#define HC 256   // HEADS*CDIM
#define L_LAYERS 2
#define NEG_SLOPE 0.2f
#define LN_EPS 1e-5f
#define SCAN_BLK 1024
#define N_SCAN_BLOCKS ((N_NODES + SCAN_BLK - 1) / SCAN_BLK)   // 49

// ---------------- device scratch (no allocations allowed) ----------------
__device__ __half g_xh[(size_t)N_NODES * HC];     // projected nodes, fp16 [N,256]
__device__ float g_as[N_NODES * HEADS];           // alpha_src [N,4]
__device__ float g_ad[N_NODES * HEADS];           // alpha_dst [N,4]
__device__ float g_exs[(size_t)N_EDGES * HEADS];  // exp(alpha), CSR order [E,4]
__device__ float g_ea_csr[(size_t)N_EDGES * 4];   // edge_attr in CSR order [E,4]
__device__ float g_z[(size_t)N_NODES * HID];      // inter-layer activations
__device__ int   g_src[N_EDGES];
__device__ int   g_dst[N_EDGES];
__device__ int   g_rank[N_EDGES];                 // rank of edge within its dst bucket
__device__ int   g_csr_src[N_EDGES];              // src id per CSR slot
__device__ int   g_rowptr[N_NODES + 1];
__device__ int   g_deg[N_NODES];
__device__ int   g_bsum[N_SCAN_BLOCKS];
__device__ int   g_boff[N_SCAN_BLOCKS];
__device__ float g_M2[2 * 12];                    // edge-attr dual matrices, both layers
__device__ int   g_is64;

// ---------------- K0a: detect dtype + zero degrees (fused) ----------------
__global__ void k_detect_zero(const int* __restrict__ ei32) {
    const int i = blockIdx.x * blockDim.x + threadIdx.x;
    if (i < N_NODES) g_deg[i] = 0;
    if (i == 0) {
        int zeros = 0;
        for (int k = 1; k < 256; k += 2) if (ei32[k] == 0) zeros++;
        g_is64 = (zeros > 100) ? 1 : 0;   // int64 data: high words all zero
    }
}

// ---------------- K0b: normalize edge index + count degrees + capture rank ----------------
__global__ void k_convert(const void* __restrict__ ei) {
    const int e = blockIdx.x * blockDim.x + threadIdx.x;
    if (e >= N_EDGES) return;
    int s, d;
    if (g_is64) {
        const long long* p = (const long long*)ei;
        s = (int)p[e]; d = (int)p[N_EDGES + e];
    } else {
        const int* p = (const int*)ei;
        s = p[e]; d = p[N_EDGES + e];
    }
    g_src[e] = s;
    g_dst[e] = d;
    g_rank[e] = atomicAdd(&g_deg[d], 1);
}

// ---------------- K0c: scan phase A — per-block exclusive scan ----------------
__global__ void __launch_bounds__(SCAN_BLK) k_scanA() {
    __shared__ int warp_sums[32];
    const int tid = threadIdx.x;
    const int i = blockIdx.x * SCAN_BLK + tid;
    const int v = (i < N_NODES) ? g_deg[i] : 0;
    int x = v;
#pragma unroll
    for (int o = 1; o < 32; o <<= 1) {
        int y = __shfl_up_sync(0xffffffffu, x, o);
        if ((tid & 31) >= o) x += y;
    }
    if ((tid & 31) == 31) warp_sums[tid >> 5] = x;
    __syncthreads();
    if (tid < 32) {
        int w = warp_sums[tid];
#pragma unroll
        for (int o = 1; o < 32; o <<= 1) {
            int y = __shfl_up_sync(0xffffffffu, w, o);
            if (tid >= o) w += y;
        }
        warp_sums[tid] = w;
    }
    __syncthreads();
    const int excl = x - v + ((tid >= 32) ? warp_sums[(tid >> 5) - 1] : 0);
    if (i < N_NODES) g_rowptr[i] = excl;
    if (tid == SCAN_BLK - 1) g_bsum[blockIdx.x] = excl + v;
}

// ---------------- K0d: scan phase B — scan the 49 block sums ----------------
__global__ void k_scanB() {
    __shared__ int s0;
    const int tid = threadIdx.x;   // 64 threads
    const int v = (tid < N_SCAN_BLOCKS) ? g_bsum[tid] : 0;
    int x = v;
#pragma unroll
    for (int o = 1; o < 32; o <<= 1) {
        int y = __shfl_up_sync(0xffffffffu, x, o);
        if ((tid & 31) >= o) x += y;
    }
    if (tid == 31) s0 = x;
    __syncthreads();
    if (tid >= 32) x += s0;
    if (tid < N_SCAN_BLOCKS) g_boff[tid] = x - v;
    if (tid == N_SCAN_BLOCKS - 1) g_rowptr[N_NODES] = x;
}

// ---------------- K0e: scan phase C — add block offsets ----------------
__global__ void __launch_bounds__(SCAN_BLK) k_scanC() {
    const int i = blockIdx.x * SCAN_BLK + threadIdx.x;
    if (i < N_NODES) g_rowptr[i] += g_boff[blockIdx.x];
}

// ---------------- K0f: fill CSR (no atomics: pos = rowptr[dst] + rank) ----------------
__global__ void k_fill(const float* __restrict__ ea) {
    const int e = blockIdx.x * blockDim.x + threadIdx.x;
    if (e >= N_EDGES) return;
    const int pos = g_rowptr[g_dst[e]] + g_rank[e];
    g_csr_src[pos] = g_src[e];
    const float* p = ea + (size_t)e * 3;
    ((float4*)g_ea_csr)[pos] = make_float4(p[0], p[1], p[2], 0.f);
}

// ---------------- K0g: M[l][d][h] for BOTH layers in one launch ----------------
__global__ void k_M_both(const float* __restrict__ We, const float* __restrict__ a_e) {
    const int t = threadIdx.x;
    if (t < 24) {
        const int l = t / 12, r = t % 12;
        const int d = r >> 2, h = r & 3;
        const float* Wel = We + (size_t)l * 3 * HC;
        const float* ael = a_e + (size_t)l * HC;
        float s = 0.f;
        for (int c = 0; c < CDIM; c++)
            s += Wel[d * HC + h * CDIM + c] * ael[h * CDIM + c];
        g_M2[t] = s;   // layout g_M2[l*12 + d*4 + h]
    }
}

// ---------------- K1: node projection (fp16 out) + alpha_src/alpha_dst ----------------
#define NB 8
__global__ void __launch_bounds__(256) k_node_proj(
    const float* __restrict__ z, const float* __restrict__ W,
    const float* __restrict__ a_s, const float* __restrict__ a_d)
{
    extern __shared__ float smem[];
    float* Wsh  = smem;                 // 64*256 = 16384 floats
    float* zshT = smem + 16384;         // [k][nb] transposed, 512 floats
    float* reds = smem + 16896;         // 64 floats
    float* redd = smem + 16960;         // 64 floats

    const int tid = threadIdx.x;
    for (int i = tid; i < (HID * HC) / 4; i += 256)
        ((float4*)Wsh)[i] = ((const float4*)W)[i];
    const float as = a_s[tid];
    const float ad = a_d[tid];
    __syncthreads();

    const int lane = tid & 31;
    const int wid = tid >> 5;
    const int nblocks = gridDim.x;

    for (int g = blockIdx.x; g * NB < N_NODES; g += nblocks) {
        const int n0 = g * NB;
        for (int i = tid; i < NB * HID; i += 256) {
            const int nb = i >> 6, k = i & 63;
            zshT[k * NB + nb] = z[(size_t)n0 * HID + i];
        }
        __syncthreads();

        float acc[NB];
#pragma unroll
        for (int nb = 0; nb < NB; nb++) acc[nb] = 0.f;

#pragma unroll
        for (int k = 0; k < HID; k++) {
            const float w = Wsh[k * HC + tid];
            const float4 za = ((float4*)zshT)[k * 2];
            const float4 zb = ((float4*)zshT)[k * 2 + 1];
            acc[0] = fmaf(za.x, w, acc[0]);
            acc[1] = fmaf(za.y, w, acc[1]);
            acc[2] = fmaf(za.z, w, acc[2]);
            acc[3] = fmaf(za.w, w, acc[3]);
            acc[4] = fmaf(zb.x, w, acc[4]);
            acc[5] = fmaf(zb.y, w, acc[5]);
            acc[6] = fmaf(zb.z, w, acc[6]);
            acc[7] = fmaf(zb.w, w, acc[7]);
        }

#pragma unroll
        for (int nb = 0; nb < NB; nb++)
            g_xh[(size_t)(n0 + nb) * HC + tid] = __float2half(acc[nb]);

        // alpha reductions use the fp32 accumulators (no fp16 error here)
#pragma unroll
        for (int nb = 0; nb < NB; nb++) {
            float ps = acc[nb] * as;
            float pd = acc[nb] * ad;
#pragma unroll
            for (int o = 16; o; o >>= 1) {
                ps += __shfl_down_sync(0xffffffffu, ps, o);
                pd += __shfl_down_sync(0xffffffffu, pd, o);
            }
            if (lane == 0) { reds[nb * 8 + wid] = ps; redd[nb * 8 + wid] = pd; }
        }
        __syncthreads();
        if (tid < 32) {
            const int nb = tid >> 2, h = tid & 3;
            g_as[(n0 + nb) * HEADS + h] = reds[nb * 8 + 2 * h] + reds[nb * 8 + 2 * h + 1];
            g_ad[(n0 + nb) * HEADS + h] = redd[nb * 8 + 2 * h] + redd[nb * 8 + 2 * h + 1];
        }
        __syncthreads();
    }
}

// ---------------- K2: fused alpha + CSR message pass + finalize ----------------
// 16 threads per dst node (R9 structure). Sweep 2 unrolled x2 with fully
// independent register banks — branch-free body, 4 x-row loads in flight.
__global__ void __launch_bounds__(256) k_gat_msg(
    int layer, float* __restrict__ zout, const float* __restrict__ bias,
    const float* __restrict__ gamma, const float* __restrict__ beta)
{
    const int t = threadIdx.x;
    const int q = t & 15;
    const int n = blockIdx.x * 16 + (t >> 4);
    const int row0 = g_rowptr[n];
    const int row1 = g_rowptr[n + 1];

    const float* M = g_M2 + layer * 12;
    const float4 ad4 = *(const float4*)(g_ad + n * 4);
    const float M0 = M[0], M1 = M[1], M2_ = M[2],  M3  = M[3];
    const float M4 = M[4], M5 = M[5], M6  = M[6],  M7  = M[7];
    const float M8 = M[8], M9 = M[9], M10 = M[10], M11 = M[11];

    // sweep 1: alpha -> exp per edge (lane-strided), denom accumulation,
    // coalesced store of ex into CSR order.
    float4 dn = make_float4(0.f, 0.f, 0.f, 0.f);
    for (int j = row0 + q; j < row1; j += 16) {
        const int s = g_csr_src[j];
        const float4 as4 = *(const float4*)(g_as + s * 4);
        const float4 ea4 = ((const float4*)g_ea_csr)[j];
        float a0 = as4.x + ad4.x + ea4.x * M0  + ea4.y * M4 + ea4.z * M8;
        float a1 = as4.y + ad4.y + ea4.x * M1  + ea4.y * M5 + ea4.z * M9;
        float a2 = as4.z + ad4.z + ea4.x * M2_ + ea4.y * M6 + ea4.z * M10;
        float a3 = as4.w + ad4.w + ea4.x * M3  + ea4.y * M7 + ea4.z * M11;
        a0 = (a0 < 0.f) ? NEG_SLOPE * a0 : a0;
        a1 = (a1 < 0.f) ? NEG_SLOPE * a1 : a1;
        a2 = (a2 < 0.f) ? NEG_SLOPE * a2 : a2;
        a3 = (a3 < 0.f) ? NEG_SLOPE * a3 : a3;
        // softmax shift-invariance + alpha ~ O(10): segment-max pass skipped.
        const float4 ex = make_float4(__expf(a0), __expf(a1), __expf(a2), __expf(a3));
        ((float4*)g_exs)[j] = ex;
        dn.x += ex.x; dn.y += ex.y; dn.z += ex.z; dn.w += ex.w;
    }
#pragma unroll
    for (int o = 8; o; o >>= 1) {
        dn.x += __shfl_xor_sync(0xffffffffu, dn.x, o);
        dn.y += __shfl_xor_sync(0xffffffffu, dn.y, o);
        dn.z += __shfl_xor_sync(0xffffffffu, dn.z, o);
        dn.w += __shfl_xor_sync(0xffffffffu, dn.w, o);
    }
    const float i0 = __frcp_rn(dn.x + 1e-16f);
    const float i1 = __frcp_rn(dn.y + 1e-16f);
    const float i2 = __frcp_rn(dn.z + 1e-16f);
    const float i3 = __frcp_rn(dn.w + 1e-16f);
    __syncwarp();   // order g_exs stores before cross-lane readback

    // sweep 2: serial edge walk, UNROLL x2 with independent banks.
    // Lane q owns channels 8*(q&7)..+7; A/C = heads 0|1, B/D = heads 2|3.
    float accA[8], accB[8], accC[8], accD[8];
#pragma unroll
    for (int i = 0; i < 8; i++) { accA[i] = 0.f; accB[i] = 0.f; accC[i] = 0.f; accD[i] = 0.f; }

    int j = row0;
    for (; j + 1 < row1; j += 2) {
        const int s1 = g_csr_src[j];
        const int s2 = g_csr_src[j + 1];
        const float4 ex1 = ((const float4*)g_exs)[j];
        const float4 ex2 = ((const float4*)g_exs)[j + 1];
        const __half* xr1 = g_xh + (size_t)s1 * HC;
        const __half* xr2 = g_xh + (size_t)s2 * HC;
        const uint4 hA = *(const uint4*)(xr1 + 8 * q);
        const uint4 hB = *(const uint4*)(xr1 + 128 + 8 * q);
        const uint4 hC = *(const uint4*)(xr2 + 8 * q);
        const uint4 hD = *(const uint4*)(xr2 + 128 + 8 * q);
        const float cA = (q < 8) ? (ex1.x * i0) : (ex1.y * i1);
        const float cB = (q < 8) ? (ex1.z * i2) : (ex1.w * i3);
        const float cC = (q < 8) ? (ex2.x * i0) : (ex2.y * i1);
        const float cD = (q < 8) ? (ex2.z * i2) : (ex2.w * i3);
        const float2 a0 = __half22float2(*(const __half2*)&hA.x);
        const float2 a1 = __half22float2(*(const __half2*)&hA.y);
        const float2 a2 = __half22float2(*(const __half2*)&hA.z);
        const float2 a3 = __half22float2(*(const __half2*)&hA.w);
        const float2 b0 = __half22float2(*(const __half2*)&hB.x);
        const float2 b1 = __half22float2(*(const __half2*)&hB.y);
        const float2 b2 = __half22float2(*(const __half2*)&hB.z);
        const float2 b3 = __half22float2(*(const __half2*)&hB.w);
        const float2 c0 = __half22float2(*(const __half2*)&hC.x);
        const float2 c1 = __half22float2(*(const __half2*)&hC.y);
        const float2 c2 = __half22float2(*(const __half2*)&hC.z);
        const float2 c3 = __half22float2(*(const __half2*)&hC.w);
        const float2 d0 = __half22float2(*(const __half2*)&hD.x);
        const float2 d1 = __half22float2(*(const __half2*)&hD.y);
        const float2 d2 = __half22float2(*(const __half2*)&hD.z);
        const float2 d3 = __half22float2(*(const __half2*)&hD.w);
        accA[0] = fmaf(cA, a0.x, accA[0]); accA[1] = fmaf(cA, a0.y, accA[1]);
        accA[2] = fmaf(cA, a1.x, accA[2]); accA[3] = fmaf(cA, a1.y, accA[3]);
        accA[4] = fmaf(cA, a2.x, accA[4]); accA[5] = fmaf(cA, a2.y, accA[5]);
        accA[6] = fmaf(cA, a3.x, accA[6]); accA[7] = fmaf(cA, a3.y, accA[7]);
        accB[0] = fmaf(cB, b0.x, accB[0]); accB[1] = fmaf(cB, b0.y, accB[1]);
        accB[2] = fmaf(cB, b1.x, accB[2]); accB[3] = fmaf(cB, b1.y, accB[3]);
        accB[4] = fmaf(cB, b2.x, accB[4]); accB[5] = fmaf(cB, b2.y, accB[5]);
        accB[6] = fmaf(cB, b3.x, accB[6]); accB[7] = fmaf(cB, b3.y, accB[7]);
        accC[0] = fmaf(cC, c0.x, accC[0]); accC[1] = fmaf(cC, c0.y, accC[1]);
        accC[2] = fmaf(cC, c1.x, accC[2]); accC[3] = fmaf(cC, c1.y, accC[3]);
        accC[4] = fmaf(cC, c2.x, accC[4]); accC[5] = fmaf(cC, c2.y, accC[5]);
        accC[6] = fmaf(cC, c3.x, accC[6]); accC[7] = fmaf(cC, c3.y, accC[7]);
        accD[0] = fmaf(cD, d0.x, accD[0]); accD[1] = fmaf(cD, d0.y, accD[1]);
        accD[2] = fmaf(cD, d1.x, accD[2]); accD[3] = fmaf(cD, d1.y, accD[3]);
        accD[4] = fmaf(cD, d2.x, accD[4]); accD[5] = fmaf(cD, d2.y, accD[5]);
        accD[6] = fmaf(cD, d3.x, accD[6]); accD[7] = fmaf(cD, d3.y, accD[7]);
    }
    if (j < row1) {
        const int s1 = g_csr_src[j];
        const float4 ex1 = ((const float4*)g_exs)[j];
        const __half* xr1 = g_xh + (size_t)s1 * HC;
        const uint4 hA = *(const uint4*)(xr1 + 8 * q);
        const uint4 hB = *(const uint4*)(xr1 + 128 + 8 * q);
        const float cA = (q < 8) ? (ex1.x * i0) : (ex1.y * i1);
        const float cB = (q < 8) ? (ex1.z * i2) : (ex1.w * i3);
        const float2 a0 = __half22float2(*(const __half2*)&hA.x);
        const float2 a1 = __half22float2(*(const __half2*)&hA.y);
        const float2 a2 = __half22float2(*(const __half2*)&hA.z);
        const float2 a3 = __half22float2(*(const __half2*)&hA.w);
        const float2 b0 = __half22float2(*(const __half2*)&hB.x);
        const float2 b1 = __half22float2(*(const __half2*)&hB.y);
        const float2 b2 = __half22float2(*(const __half2*)&hB.z);
        const float2 b3 = __half22float2(*(const __half2*)&hB.w);
        accA[0] = fmaf(cA, a0.x, accA[0]); accA[1] = fmaf(cA, a0.y, accA[1]);
        accA[2] = fmaf(cA, a1.x, accA[2]); accA[3] = fmaf(cA, a1.y, accA[3]);
        accA[4] = fmaf(cA, a2.x, accA[4]); accA[5] = fmaf(cA, a2.y, accA[5]);
        accA[6] = fmaf(cA, a3.x, accA[6]); accA[7] = fmaf(cA, a3.y, accA[7]);
        accB[0] = fmaf(cB, b0.x, accB[0]); accB[1] = fmaf(cB, b0.y, accB[1]);
        accB[2] = fmaf(cB, b1.x, accB[2]); accB[3] = fmaf(cB, b1.y, accB[3]);
        accB[4] = fmaf(cB, b2.x, accB[4]); accB[5] = fmaf(cB, b2.y, accB[5]);
        accB[6] = fmaf(cB, b3.x, accB[6]); accB[7] = fmaf(cB, b3.y, accB[7]);
    }

    // combine banks + head-halves across the 8-lane pairs
    float tot[8];
#pragma unroll
    for (int i = 0; i < 8; i++) {
        float v = (accA[i] + accC[i]) + (accB[i] + accD[i]);
        v += __shfl_xor_sync(0xffffffffu, v, 8);
        tot[i] = v;   // lane q now has full sum over 4 heads for c=8*(q&7)+i
    }

    // finalize: head-mean + bias + LN + SiLU (values mirrored in lane pairs)
    const int c0i = 8 * (q & 7);
    float v[8];
    float s = 0.f;
#pragma unroll
    for (int i = 0; i < 8; i++) {
        v[i] = 0.25f * tot[i] + bias[c0i + i];
        s += v[i];
    }
#pragma unroll
    for (int o = 4; o; o >>= 1) s += __shfl_xor_sync(0xffffffffu, s, o);
    const float mu = s * (1.f / 64.f);
    float qs = 0.f;
#pragma unroll
    for (int i = 0; i < 8; i++) {
        v[i] -= mu;
        qs += v[i] * v[i];
    }
#pragma unroll
    for (int o = 4; o; o >>= 1) qs += __shfl_xor_sync(0xffffffffu, qs, o);
    const float rs = rsqrtf(qs * (1.f / 64.f) + LN_EPS);

    if (q < 8) {
        float y[8];
#pragma unroll
        for (int i = 0; i < 8; i++) {
            const float tv = v[i] * rs * gamma[c0i + i] + beta[c0i + i];
            y[i] = tv / (1.f + __expf(-tv));
        }
        float4* dst = (float4*)(zout + (size_t)n * HID + c0i);
        dst[0] = make_float4(y[0], y[1], y[2], y[3]);
        dst[1] = make_float4(y[4], y[5], y[6], y[7]);
    }
}

// ---------------- launcher ----------------
extern "C" void kernel_launch(void* const* d_in, const int* in_sizes, int n_in,
                              void* d_out, int out_size) {
    (void)in_sizes; (void)n_in; (void)out_size;
    const float* h     = (const float*)d_in[1];
    const void*  ei    = d_in[2];
    const float* ea    = (const float*)d_in[3];
    const float* W     = (const float*)d_in[4];
    const float* We    = (const float*)d_in[5];
    const float* as_   = (const float*)d_in[6];
    const float* ad_   = (const float*)d_in[7];
    const float* ae_   = (const float*)d_in[8];
    const float* bias  = (const float*)d_in[9];
    const float* gamma = (const float*)d_in[10];
    const float* beta  = (const float*)d_in[11];
    float* out = (float*)d_out;

    const int smem_bytes = 17024 * 4;   // 68096 B
    cudaFuncSetAttribute(k_node_proj, cudaFuncAttributeMaxDynamicSharedMemorySize, smem_bytes);

    float* zbuf = nullptr;
    cudaGetSymbolAddress((void**)&zbuf, g_z);

    // ---- preamble: CSR build + both layers' M (all layer-invariant) ----
    k_detect_zero<<<(N_NODES + 255) / 256, 256>>>((const int*)ei);
    k_convert<<<(N_EDGES + 255) / 256, 256>>>(ei);
    k_scanA<<<N_SCAN_BLOCKS, SCAN_BLK>>>();
    k_scanB<<<1, 64>>>();
    k_scanC<<<N_SCAN_BLOCKS, SCAN_BLK>>>();
    k_fill<<<(N_EDGES + 255) / 256, 256>>>(ea);
    k_M_both<<<1, 32>>>(We, ae_);

    const float* zin = h;
    for (int l = 0; l < L_LAYERS; l++) {
        k_node_proj<<<444, 256, smem_bytes>>>(zin, W + (size_t)l * HID * HC,
                                              as_ + (size_t)l * HC, ad_ + (size_t)l * HC);
        k_gat_msg<<<N_NODES / 16, 256>>>(l, l == 0 ? zbuf : out,
                                         bias + (size_t)l * HID,
                                         gamma + (size_t)l * HID,
                                         beta + (size_t)l * HID);
        zin = zbuf;
    }
}

// round 13
// speedup vs baseline: 1.1199x; 1.1056x over previous
#include <cuda_runtime.h>
#include <cuda_fp16.h>
#include <cstdint>

#define N_NODES 50000
#define N_EDGES 800000
#define HID 64
#define HEADS 4
#define CDIM 64
#define HC 256   // HEADS*CDIM
#define L_LAYERS 2
#define NEG_SLOPE 0.2f
#define LN_EPS 1e-5f
#define SCAN_BLK 1024
#define N_SCAN_BLOCKS ((N_NODES + SCAN_BLK - 1) / SCAN_BLK)   // 49

// ---------------- device scratch (no allocations allowed) ----------------
__device__ __half g_xh[(size_t)N_NODES * HC];     // projected nodes, fp16 [N,256]
__device__ float g_as[N_NODES * HEADS];           // alpha_src [N,4]
__device__ float g_ad[N_NODES * HEADS];           // alpha_dst [N,4]
__device__ float g_exs[(size_t)N_EDGES * HEADS];  // exp(alpha), CSR order [E,4]
__device__ float g_ea_csr[(size_t)N_EDGES * 4];   // edge_attr in CSR order [E,4]
__device__ float g_z[(size_t)N_NODES * HID];      // inter-layer activations
__device__ int   g_src[N_EDGES];
__device__ int   g_dst[N_EDGES];
__device__ int   g_rank[N_EDGES];                 // rank of edge within its dst bucket
__device__ int   g_csr_src[N_EDGES];              // src id per CSR slot
__device__ int   g_rowptr[N_NODES + 1];
__device__ int   g_deg[N_NODES];
__device__ int   g_bsum[N_SCAN_BLOCKS];
__device__ int   g_boff[N_SCAN_BLOCKS];
__device__ float g_M2[2 * 12];                    // edge-attr dual matrices, both layers
__device__ int   g_is64;

// ---------------- K0a: detect dtype + zero degrees + M (fused) ----------------
__global__ void k_detect_zero_M(const int* __restrict__ ei32,
                                const float* __restrict__ We,
                                const float* __restrict__ a_e) {
    const int i = blockIdx.x * blockDim.x + threadIdx.x;
    if (i < N_NODES) g_deg[i] = 0;
    if (i == 0) {
        int zeros = 0;
        for (int k = 1; k < 256; k += 2) if (ei32[k] == 0) zeros++;
        g_is64 = (zeros > 100) ? 1 : 0;   // int64 data: high words all zero
    }
    // block 0, threads 32..55: both layers' M[l][d][h] (independent of is64)
    if (blockIdx.x == 0 && threadIdx.x >= 32 && threadIdx.x < 56) {
        const int t = threadIdx.x - 32;
        const int l = t / 12, r = t % 12;
        const int d = r >> 2, h = r & 3;
        const float* Wel = We + (size_t)l * 3 * HC;
        const float* ael = a_e + (size_t)l * HC;
        float s = 0.f;
        for (int c = 0; c < CDIM; c++)
            s += Wel[d * HC + h * CDIM + c] * ael[h * CDIM + c];
        g_M2[t] = s;   // layout g_M2[l*12 + d*4 + h]
    }
}

// ---------------- K0b: normalize edge index + count degrees + capture rank ----------------
__global__ void k_convert(const void* __restrict__ ei) {
    const int e = blockIdx.x * blockDim.x + threadIdx.x;
    if (e >= N_EDGES) return;
    int s, d;
    if (g_is64) {
        const long long* p = (const long long*)ei;
        s = (int)p[e]; d = (int)p[N_EDGES + e];
    } else {
        const int* p = (const int*)ei;
        s = p[e]; d = p[N_EDGES + e];
    }
    g_src[e] = s;
    g_dst[e] = d;
    g_rank[e] = atomicAdd(&g_deg[d], 1);
}

// ---------------- K0c: scan phase A — per-block exclusive scan ----------------
__global__ void __launch_bounds__(SCAN_BLK) k_scanA() {
    __shared__ int warp_sums[32];
    const int tid = threadIdx.x;
    const int i = blockIdx.x * SCAN_BLK + tid;
    const int v = (i < N_NODES) ? g_deg[i] : 0;
    int x = v;
#pragma unroll
    for (int o = 1; o < 32; o <<= 1) {
        int y = __shfl_up_sync(0xffffffffu, x, o);
        if ((tid & 31) >= o) x += y;
    }
    if ((tid & 31) == 31) warp_sums[tid >> 5] = x;
    __syncthreads();
    if (tid < 32) {
        int w = warp_sums[tid];
#pragma unroll
        for (int o = 1; o < 32; o <<= 1) {
            int y = __shfl_up_sync(0xffffffffu, w, o);
            if (tid >= o) w += y;
        }
        warp_sums[tid] = w;
    }
    __syncthreads();
    const int excl = x - v + ((tid >= 32) ? warp_sums[(tid >> 5) - 1] : 0);
    if (i < N_NODES) g_rowptr[i] = excl;
    if (tid == SCAN_BLK - 1) g_bsum[blockIdx.x] = excl + v;
}

// ---------------- K0d: scan phase B — scan the 49 block sums ----------------
__global__ void k_scanB() {
    __shared__ int s0;
    const int tid = threadIdx.x;   // 64 threads
    const int v = (tid < N_SCAN_BLOCKS) ? g_bsum[tid] : 0;
    int x = v;
#pragma unroll
    for (int o = 1; o < 32; o <<= 1) {
        int y = __shfl_up_sync(0xffffffffu, x, o);
        if ((tid & 31) >= o) x += y;
    }
    if (tid == 31) s0 = x;
    __syncthreads();
    if (tid >= 32) x += s0;
    if (tid < N_SCAN_BLOCKS) g_boff[tid] = x - v;
    if (tid == N_SCAN_BLOCKS - 1) g_rowptr[N_NODES] = x;
}

// ---------------- K0e: scan phase C — add block offsets ----------------
__global__ void __launch_bounds__(SCAN_BLK) k_scanC() {
    const int i = blockIdx.x * SCAN_BLK + threadIdx.x;
    if (i < N_NODES) g_rowptr[i] += g_boff[blockIdx.x];
}

// ---------------- K0f: fill CSR (no atomics: pos = rowptr[dst] + rank) ----------------
__global__ void k_fill(const float* __restrict__ ea) {
    const int e = blockIdx.x * blockDim.x + threadIdx.x;
    if (e >= N_EDGES) return;
    const int pos = g_rowptr[g_dst[e]] + g_rank[e];
    g_csr_src[pos] = g_src[e];
    const float* p = ea + (size_t)e * 3;
    ((float4*)g_ea_csr)[pos] = make_float4(p[0], p[1], p[2], 0.f);
}

// ---------------- K1: node projection (fp16 out) + alpha_src/alpha_dst ----------------
#define NB 8
__global__ void __launch_bounds__(256) k_node_proj(
    const float* __restrict__ z, const float* __restrict__ W,
    const float* __restrict__ a_s, const float* __restrict__ a_d)
{
    extern __shared__ float smem[];
    float* Wsh  = smem;                 // 64*256 = 16384 floats
    float* zshT = smem + 16384;         // [k][nb] transposed, 512 floats
    float* reds = smem + 16896;         // 64 floats
    float* redd = smem + 16960;         // 64 floats

    const int tid = threadIdx.x;
    for (int i = tid; i < (HID * HC) / 4; i += 256)
        ((float4*)Wsh)[i] = ((const float4*)W)[i];
    const float as = a_s[tid];
    const float ad = a_d[tid];
    __syncthreads();

    const int lane = tid & 31;
    const int wid = tid >> 5;
    const int nblocks = gridDim.x;

    for (int g = blockIdx.x; g * NB < N_NODES; g += nblocks) {
        const int n0 = g * NB;
        for (int i = tid; i < NB * HID; i += 256) {
            const int nb = i >> 6, k = i & 63;
            zshT[k * NB + nb] = z[(size_t)n0 * HID + i];
        }
        __syncthreads();

        float acc[NB];
#pragma unroll
        for (int nb = 0; nb < NB; nb++) acc[nb] = 0.f;

#pragma unroll
        for (int k = 0; k < HID; k++) {
            const float w = Wsh[k * HC + tid];
            const float4 za = ((float4*)zshT)[k * 2];
            const float4 zb = ((float4*)zshT)[k * 2 + 1];
            acc[0] = fmaf(za.x, w, acc[0]);
            acc[1] = fmaf(za.y, w, acc[1]);
            acc[2] = fmaf(za.z, w, acc[2]);
            acc[3] = fmaf(za.w, w, acc[3]);
            acc[4] = fmaf(zb.x, w, acc[4]);
            acc[5] = fmaf(zb.y, w, acc[5]);
            acc[6] = fmaf(zb.z, w, acc[6]);
            acc[7] = fmaf(zb.w, w, acc[7]);
        }

#pragma unroll
        for (int nb = 0; nb < NB; nb++)
            g_xh[(size_t)(n0 + nb) * HC + tid] = __float2half(acc[nb]);

        // alpha reductions use the fp32 accumulators (no fp16 error here)
#pragma unroll
        for (int nb = 0; nb < NB; nb++) {
            float ps = acc[nb] * as;
            float pd = acc[nb] * ad;
#pragma unroll
            for (int o = 16; o; o >>= 1) {
                ps += __shfl_down_sync(0xffffffffu, ps, o);
                pd += __shfl_down_sync(0xffffffffu, pd, o);
            }
            if (lane == 0) { reds[nb * 8 + wid] = ps; redd[nb * 8 + wid] = pd; }
        }
        __syncthreads();
        if (tid < 32) {
            const int nb = tid >> 2, h = tid & 3;
            g_as[(n0 + nb) * HEADS + h] = reds[nb * 8 + 2 * h] + reds[nb * 8 + 2 * h + 1];
            g_ad[(n0 + nb) * HEADS + h] = redd[nb * 8 + 2 * h] + redd[nb * 8 + 2 * h + 1];
        }
        __syncthreads();
    }
}

// ---------------- K2: fused alpha + CSR message pass + finalize ----------------
// 16 threads per dst node (R9 structure — the best measured config).
__global__ void __launch_bounds__(256) k_gat_msg(
    int layer, float* __restrict__ zout, const float* __restrict__ bias,
    const float* __restrict__ gamma, const float* __restrict__ beta)
{
    const int t = threadIdx.x;
    const int q = t & 15;
    const int n = blockIdx.x * 16 + (t >> 4);
    const int row0 = g_rowptr[n];
    const int row1 = g_rowptr[n + 1];

    const float* M = g_M2 + layer * 12;
    const float4 ad4 = *(const float4*)(g_ad + n * 4);
    const float M0 = M[0], M1 = M[1], M2_ = M[2],  M3  = M[3];
    const float M4 = M[4], M5 = M[5], M6  = M[6],  M7  = M[7];
    const float M8 = M[8], M9 = M[9], M10 = M[10], M11 = M[11];

    // sweep 1: alpha -> exp per edge (lane-strided), denom accumulation,
    // coalesced store of ex into CSR order.
    float4 dn = make_float4(0.f, 0.f, 0.f, 0.f);
    for (int j = row0 + q; j < row1; j += 16) {
        const int s = g_csr_src[j];
        const float4 as4 = *(const float4*)(g_as + s * 4);
        const float4 ea4 = ((const float4*)g_ea_csr)[j];
        float a0 = as4.x + ad4.x + ea4.x * M0  + ea4.y * M4 + ea4.z * M8;
        float a1 = as4.y + ad4.y + ea4.x * M1  + ea4.y * M5 + ea4.z * M9;
        float a2 = as4.z + ad4.z + ea4.x * M2_ + ea4.y * M6 + ea4.z * M10;
        float a3 = as4.w + ad4.w + ea4.x * M3  + ea4.y * M7 + ea4.z * M11;
        a0 = (a0 < 0.f) ? NEG_SLOPE * a0 : a0;
        a1 = (a1 < 0.f) ? NEG_SLOPE * a1 : a1;
        a2 = (a2 < 0.f) ? NEG_SLOPE * a2 : a2;
        a3 = (a3 < 0.f) ? NEG_SLOPE * a3 : a3;
        // softmax shift-invariance + alpha ~ O(10): segment-max pass skipped.
        const float4 ex = make_float4(__expf(a0), __expf(a1), __expf(a2), __expf(a3));
        ((float4*)g_exs)[j] = ex;
        dn.x += ex.x; dn.y += ex.y; dn.z += ex.z; dn.w += ex.w;
    }
#pragma unroll
    for (int o = 8; o; o >>= 1) {
        dn.x += __shfl_xor_sync(0xffffffffu, dn.x, o);
        dn.y += __shfl_xor_sync(0xffffffffu, dn.y, o);
        dn.z += __shfl_xor_sync(0xffffffffu, dn.z, o);
        dn.w += __shfl_xor_sync(0xffffffffu, dn.w, o);
    }
    const float i0 = __frcp_rn(dn.x + 1e-16f);
    const float i1 = __frcp_rn(dn.y + 1e-16f);
    const float i2 = __frcp_rn(dn.z + 1e-16f);
    const float i3 = __frcp_rn(dn.w + 1e-16f);
    __syncwarp();   // order g_exs stores before cross-lane readback

    // sweep 2: serial edge walk; lane q owns channels 8*(q&7)..+7.
    // Load A covers head (q<8 ? 0 : 1), load B covers head (q<8 ? 2 : 3).
    float accA[8], accB[8];
#pragma unroll
    for (int i = 0; i < 8; i++) { accA[i] = 0.f; accB[i] = 0.f; }

    for (int j = row0; j < row1; j++) {
        const int s = g_csr_src[j];
        const float4 ex = ((const float4*)g_exs)[j];
        const float cA = (q < 8) ? (ex.x * i0) : (ex.y * i1);
        const float cB = (q < 8) ? (ex.z * i2) : (ex.w * i3);
        const __half* xr = g_xh + (size_t)s * HC;
        const uint4 hA = *(const uint4*)(xr + 8 * q);          // heads 0|1
        const uint4 hB = *(const uint4*)(xr + 128 + 8 * q);    // heads 2|3
        const float2 a0 = __half22float2(*(const __half2*)&hA.x);
        const float2 a1 = __half22float2(*(const __half2*)&hA.y);
        const float2 a2 = __half22float2(*(const __half2*)&hA.z);
        const float2 a3 = __half22float2(*(const __half2*)&hA.w);
        const float2 b0 = __half22float2(*(const __half2*)&hB.x);
        const float2 b1 = __half22float2(*(const __half2*)&hB.y);
        const float2 b2 = __half22float2(*(const __half2*)&hB.z);
        const float2 b3 = __half22float2(*(const __half2*)&hB.w);
        accA[0] = fmaf(cA, a0.x, accA[0]); accA[1] = fmaf(cA, a0.y, accA[1]);
        accA[2] = fmaf(cA, a1.x, accA[2]); accA[3] = fmaf(cA, a1.y, accA[3]);
        accA[4] = fmaf(cA, a2.x, accA[4]); accA[5] = fmaf(cA, a2.y, accA[5]);
        accA[6] = fmaf(cA, a3.x, accA[6]); accA[7] = fmaf(cA, a3.y, accA[7]);
        accB[0] = fmaf(cB, b0.x, accB[0]); accB[1] = fmaf(cB, b0.y, accB[1]);
        accB[2] = fmaf(cB, b1.x, accB[2]); accB[3] = fmaf(cB, b1.y, accB[3]);
        accB[4] = fmaf(cB, b2.x, accB[4]); accB[5] = fmaf(cB, b2.y, accB[5]);
        accB[6] = fmaf(cB, b3.x, accB[6]); accB[7] = fmaf(cB, b3.y, accB[7]);
    }

    // combine the two head-halves across the 8-lane pairs
    float tot[8];
#pragma unroll
    for (int i = 0; i < 8; i++) {
        float v = accA[i] + accB[i];
        v += __shfl_xor_sync(0xffffffffu, v, 8);
        tot[i] = v;   // lane q now has full sum over 4 heads for c=8*(q&7)+i
    }

    // finalize: head-mean + bias + LN + SiLU (values mirrored in lane pairs)
    const int c0i = 8 * (q & 7);
    float v[8];
    float s = 0.f;
#pragma unroll
    for (int i = 0; i < 8; i++) {
        v[i] = 0.25f * tot[i] + bias[c0i + i];
        s += v[i];
    }
#pragma unroll
    for (int o = 4; o; o >>= 1) s += __shfl_xor_sync(0xffffffffu, s, o);
    const float mu = s * (1.f / 64.f);
    float qs = 0.f;
#pragma unroll
    for (int i = 0; i < 8; i++) {
        v[i] -= mu;
        qs += v[i] * v[i];
    }
#pragma unroll
    for (int o = 4; o; o >>= 1) qs += __shfl_xor_sync(0xffffffffu, qs, o);
    const float rs = rsqrtf(qs * (1.f / 64.f) + LN_EPS);

    if (q < 8) {
        float y[8];
#pragma unroll
        for (int i = 0; i < 8; i++) {
            const float tv = v[i] * rs * gamma[c0i + i] + beta[c0i + i];
            y[i] = tv / (1.f + __expf(-tv));
        }
        float4* dst = (float4*)(zout + (size_t)n * HID + c0i);
        dst[0] = make_float4(y[0], y[1], y[2], y[3]);
        dst[1] = make_float4(y[4], y[5], y[6], y[7]);
    }
}

// ---------------- launcher ----------------
extern "C" void kernel_launch(void* const* d_in, const int* in_sizes, int n_in,
                              void* d_out, int out_size) {
    (void)in_sizes; (void)n_in; (void)out_size;
    const float* h     = (const float*)d_in[1];
    const void*  ei    = d_in[2];
    const float* ea    = (const float*)d_in[3];
    const float* W     = (const float*)d_in[4];
    const float* We    = (const float*)d_in[5];
    const float* as_   = (const float*)d_in[6];
    const float* ad_   = (const float*)d_in[7];
    const float* ae_   = (const float*)d_in[8];
    const float* bias  = (const float*)d_in[9];
    const float* gamma = (const float*)d_in[10];
    const float* beta  = (const float*)d_in[11];
    float* out = (float*)d_out;

    const int smem_bytes = 17024 * 4;   // 68096 B
    cudaFuncSetAttribute(k_node_proj, cudaFuncAttributeMaxDynamicSharedMemorySize, smem_bytes);

    float* zbuf = nullptr;
    cudaGetSymbolAddress((void**)&zbuf, g_z);

    // ---- preamble: CSR build + both layers' M (all layer-invariant) ----
    k_detect_zero_M<<<(N_NODES + 255) / 256, 256>>>((const int*)ei, We, ae_);
    k_convert<<<(N_EDGES + 255) / 256, 256>>>(ei);
    k_scanA<<<N_SCAN_BLOCKS, SCAN_BLK>>>();
    k_scanB<<<1, 64>>>();
    k_scanC<<<N_SCAN_BLOCKS, SCAN_BLK>>>();
    k_fill<<<(N_EDGES + 255) / 256, 256>>>(ea);

    const float* zin = h;
    for (int l = 0; l < L_LAYERS; l++) {
        k_node_proj<<<444, 256, smem_bytes>>>(zin, W + (size_t)l * HID * HC,
                                              as_ + (size_t)l * HC, ad_ + (size_t)l * HC);
        k_gat_msg<<<N_NODES / 16, 256>>>(l, l == 0 ? zbuf : out,
                                         bias + (size_t)l * HID,
                                         gamma + (size_t)l * HID,
                                         beta + (size_t)l * HID);
        zin = zbuf;
    }
}

// round 14
// speedup vs baseline: 1.5277x; 1.3642x over previous
#include <cuda_runtime.h>
#include <cuda_fp16.h>
#include <cstdint>

#define N_NODES 50000
#define N_EDGES 800000
#define HID 64
#define HEADS 4
#define CDIM 64
#define HC 256   // HEADS*CDIM
#define L_LAYERS 2
#define NEG_SLOPE 0.2f
#define LN_EPS 1e-5f
#define SCAN_BLK 1024
#define N_SCAN_BLOCKS ((N_NODES + SCAN_BLK - 1) / SCAN_BLK)   // 49
#define N_PAD 32
#define PROJ_BLOCKS ((N_NODES + 31) / 32)                     // 1563

// ---------------- device scratch (no allocations allowed) ----------------
__device__ __half g_xh[(size_t)N_NODES * HC];     // projected nodes, fp16 [N,256]
__device__ __half g_zh[(size_t)(N_NODES + N_PAD) * HID]; // activations, fp16 (padded)
__device__ __half g_wt[(size_t)L_LAYERS * HC * HID];     // W transposed fp16 [l][n][k]
__device__ float g_as[N_NODES * HEADS];           // alpha_src [N,4]
__device__ float g_ad[N_NODES * HEADS];           // alpha_dst [N,4]
__device__ float g_exs[(size_t)N_EDGES * HEADS];  // exp(alpha), CSR order [E,4]
__device__ float g_ea_csr[(size_t)N_EDGES * 4];   // edge_attr in CSR order [E,4]
__device__ int   g_src[N_EDGES];
__device__ int   g_dst[N_EDGES];
__device__ int   g_rank[N_EDGES];                 // rank of edge within its dst bucket
__device__ int   g_csr_src[N_EDGES];              // src id per CSR slot
__device__ int   g_rowptr[N_NODES + 1];
__device__ int   g_deg[N_NODES];
__device__ int   g_bsum[N_SCAN_BLOCKS];
__device__ int   g_boff[N_SCAN_BLOCKS];
__device__ float g_M2[2 * 12];                    // edge-attr dual matrices, both layers
__device__ int   g_is64;

// ---------------- K0a: detect dtype + zero degrees + M (fused) ----------------
__global__ void k_detect_zero_M(const int* __restrict__ ei32,
                                const float* __restrict__ We,
                                const float* __restrict__ a_e) {
    const int i = blockIdx.x * blockDim.x + threadIdx.x;
    if (i < N_NODES) g_deg[i] = 0;
    if (i == 0) {
        int zeros = 0;
        for (int k = 1; k < 256; k += 2) if (ei32[k] == 0) zeros++;
        g_is64 = (zeros > 100) ? 1 : 0;   // int64 data: high words all zero
    }
    if (blockIdx.x == 0 && threadIdx.x >= 32 && threadIdx.x < 56) {
        const int t = threadIdx.x - 32;
        const int l = t / 12, r = t % 12;
        const int d = r >> 2, h = r & 3;
        const float* Wel = We + (size_t)l * 3 * HC;
        const float* ael = a_e + (size_t)l * HC;
        float s = 0.f;
        for (int c = 0; c < CDIM; c++)
            s += Wel[d * HC + h * CDIM + c] * ael[h * CDIM + c];
        g_M2[t] = s;   // layout g_M2[l*12 + d*4 + h]
    }
}

// ---------------- K0b: normalize edge index + count degrees + capture rank ----------------
__global__ void k_convert(const void* __restrict__ ei) {
    const int e = blockIdx.x * blockDim.x + threadIdx.x;
    if (e >= N_EDGES) return;
    int s, d;
    if (g_is64) {
        const long long* p = (const long long*)ei;
        s = (int)p[e]; d = (int)p[N_EDGES + e];
    } else {
        const int* p = (const int*)ei;
        s = p[e]; d = p[N_EDGES + e];
    }
    g_src[e] = s;
    g_dst[e] = d;
    g_rank[e] = atomicAdd(&g_deg[d], 1);
}

// ---------------- K0c: scan phase A — per-block exclusive scan ----------------
__global__ void __launch_bounds__(SCAN_BLK) k_scanA() {
    __shared__ int warp_sums[32];
    const int tid = threadIdx.x;
    const int i = blockIdx.x * SCAN_BLK + tid;
    const int v = (i < N_NODES) ? g_deg[i] : 0;
    int x = v;
#pragma unroll
    for (int o = 1; o < 32; o <<= 1) {
        int y = __shfl_up_sync(0xffffffffu, x, o);
        if ((tid & 31) >= o) x += y;
    }
    if ((tid & 31) == 31) warp_sums[tid >> 5] = x;
    __syncthreads();
    if (tid < 32) {
        int w = warp_sums[tid];
#pragma unroll
        for (int o = 1; o < 32; o <<= 1) {
            int y = __shfl_up_sync(0xffffffffu, w, o);
            if (tid >= o) w += y;
        }
        warp_sums[tid] = w;
    }
    __syncthreads();
    const int excl = x - v + ((tid >= 32) ? warp_sums[(tid >> 5) - 1] : 0);
    if (i < N_NODES) g_rowptr[i] = excl;
    if (tid == SCAN_BLK - 1) g_bsum[blockIdx.x] = excl + v;
}

// ---------------- K0d: scan phase B — scan the 49 block sums ----------------
__global__ void k_scanB() {
    __shared__ int s0;
    const int tid = threadIdx.x;   // 64 threads
    const int v = (tid < N_SCAN_BLOCKS) ? g_bsum[tid] : 0;
    int x = v;
#pragma unroll
    for (int o = 1; o < 32; o <<= 1) {
        int y = __shfl_up_sync(0xffffffffu, x, o);
        if ((tid & 31) >= o) x += y;
    }
    if (tid == 31) s0 = x;
    __syncthreads();
    if (tid >= 32) x += s0;
    if (tid < N_SCAN_BLOCKS) g_boff[tid] = x - v;
    if (tid == N_SCAN_BLOCKS - 1) g_rowptr[N_NODES] = x;
}

// ---------------- K0e: scan phase C — add block offsets ----------------
__global__ void __launch_bounds__(SCAN_BLK) k_scanC() {
    const int i = blockIdx.x * SCAN_BLK + threadIdx.x;
    if (i < N_NODES) g_rowptr[i] += g_boff[blockIdx.x];
}

// ---------------- K0f: fill CSR (no atomics: pos = rowptr[dst] + rank) ----------------
__global__ void k_fill(const float* __restrict__ ea) {
    const int e = blockIdx.x * blockDim.x + threadIdx.x;
    if (e >= N_EDGES) return;
    const int pos = g_rowptr[g_dst[e]] + g_rank[e];
    g_csr_src[pos] = g_src[e];
    const float* p = ea + (size_t)e * 3;
    ((float4*)g_ea_csr)[pos] = make_float4(p[0], p[1], p[2], 0.f);
}

// ---------------- K0g: convert h -> fp16 g_zh (with zero pad) ----------------
__global__ void k_h2h(const float* __restrict__ h) {
    const int i = blockIdx.x * blockDim.x + threadIdx.x;
    const int n_main = (N_NODES * HID) / 2;
    if (i < n_main) {
        const float2 v = ((const float2*)h)[i];
        ((__half2*)g_zh)[i] = __floats2half2_rn(v.x, v.y);
    } else if (i < n_main + (N_PAD * HID) / 2) {
        ((__half2*)g_zh)[i] = __floats2half2_rn(0.f, 0.f);
    }
}

// ---------------- K0h: transpose+convert W -> g_wt[l][n][k] fp16 ----------------
__global__ void k_wt(const float* __restrict__ W) {
    const int i = blockIdx.x * blockDim.x + threadIdx.x;   // over 2*256*64
    if (i >= L_LAYERS * HC * HID) return;
    const int l = i / (HC * HID);
    const int r = i % (HC * HID);
    const int n = r / HID;
    const int k = r % HID;
    g_wt[i] = __float2half(W[(size_t)l * HID * HC + (size_t)k * HC + n]);
}

// ---------------- K1: tensor-core node projection + alpha_src/alpha_dst ----------------
// Block = 256 thr = 8 warps; block tile 32 rows x 256 cols.
// Warp w: rows 16*(w>>2), cols 64*(w&3) (exactly one head). mma.m16n8k16.
__global__ void __launch_bounds__(256) k_proj_mma(
    const __half* __restrict__ wt,    // this layer, [256][64]
    const float* __restrict__ a_s, const float* __restrict__ a_d)
{
    const int w = threadIdx.x >> 5;
    const int lane = threadIdx.x & 31;
    const int gid = lane >> 2;     // 0..7
    const int qd = lane & 3;       // quad index
    const int head = w & 3;
    const int n0 = blockIdx.x * 32 + (w >> 2) * 16;
    const int c0 = head * 64;

    const int r0 = n0 + gid;
    const __half* zrow0 = g_zh + (size_t)r0 * HID;
    const __half* zrow8 = g_zh + (size_t)(r0 + 8) * HID;

    float acc[8][4];
#pragma unroll
    for (int t = 0; t < 8; t++) { acc[t][0]=0.f; acc[t][1]=0.f; acc[t][2]=0.f; acc[t][3]=0.f; }

#pragma unroll
    for (int ks = 0; ks < 4; ks++) {
        const int k0 = ks * 16 + qd * 2;
        const uint32_t a0 = *(const uint32_t*)(zrow0 + k0);
        const uint32_t a1 = *(const uint32_t*)(zrow8 + k0);
        const uint32_t a2 = *(const uint32_t*)(zrow0 + k0 + 8);
        const uint32_t a3 = *(const uint32_t*)(zrow8 + k0 + 8);
#pragma unroll
        for (int t = 0; t < 8; t++) {
            const __half* wrow = wt + (size_t)(c0 + t * 8 + gid) * HID;
            const uint32_t b0 = *(const uint32_t*)(wrow + k0);
            const uint32_t b1 = *(const uint32_t*)(wrow + k0 + 8);
            asm volatile(
                "mma.sync.aligned.m16n8k16.row.col.f32.f16.f16.f32 "
                "{%0,%1,%2,%3}, {%4,%5,%6,%7}, {%8,%9}, {%0,%1,%2,%3};\n"
                : "+f"(acc[t][0]), "+f"(acc[t][1]), "+f"(acc[t][2]), "+f"(acc[t][3])
                : "r"(a0), "r"(a1), "r"(a2), "r"(a3), "r"(b0), "r"(b1));
        }
    }

    // epilogue: store x (fp16) + per-head alpha partials (fp32)
    const bool ok0 = (r0 < N_NODES);
    const bool ok8 = (r0 + 8 < N_NODES);
    float as0 = 0.f, as8 = 0.f, ad0 = 0.f, ad8 = 0.f;
#pragma unroll
    for (int t = 0; t < 8; t++) {
        const int jc = c0 + t * 8 + qd * 2;
        if (ok0) *(__half2*)(g_xh + (size_t)r0 * HC + jc) = __floats2half2_rn(acc[t][0], acc[t][1]);
        if (ok8) *(__half2*)(g_xh + (size_t)(r0 + 8) * HC + jc) = __floats2half2_rn(acc[t][2], acc[t][3]);
        const float s0 = a_s[jc], s1 = a_s[jc + 1];
        const float d0 = a_d[jc], d1 = a_d[jc + 1];
        as0 += acc[t][0] * s0 + acc[t][1] * s1;
        as8 += acc[t][2] * s0 + acc[t][3] * s1;
        ad0 += acc[t][0] * d0 + acc[t][1] * d1;
        ad8 += acc[t][2] * d0 + acc[t][3] * d1;
    }
#pragma unroll
    for (int o = 1; o < 4; o <<= 1) {
        as0 += __shfl_xor_sync(0xffffffffu, as0, o);
        as8 += __shfl_xor_sync(0xffffffffu, as8, o);
        ad0 += __shfl_xor_sync(0xffffffffu, ad0, o);
        ad8 += __shfl_xor_sync(0xffffffffu, ad8, o);
    }
    if (qd == 0) {
        if (ok0) { g_as[r0 * 4 + head] = as0; g_ad[r0 * 4 + head] = ad0; }
        if (ok8) { g_as[(r0 + 8) * 4 + head] = as8; g_ad[(r0 + 8) * 4 + head] = ad8; }
    }
}

// ---------------- K2: fused alpha + CSR message pass + finalize ----------------
// 16 threads per dst node (best measured config). Layer 0 writes fp16 g_zh;
// layer 1 writes fp32 out.
__global__ void __launch_bounds__(256) k_gat_msg(
    int layer, float* __restrict__ zout, const float* __restrict__ bias,
    const float* __restrict__ gamma, const float* __restrict__ beta)
{
    const int t = threadIdx.x;
    const int q = t & 15;
    const int n = blockIdx.x * 16 + (t >> 4);
    const int row0 = g_rowptr[n];
    const int row1 = g_rowptr[n + 1];

    const float* M = g_M2 + layer * 12;
    const float4 ad4 = *(const float4*)(g_ad + n * 4);
    const float M0 = M[0], M1 = M[1], M2_ = M[2],  M3  = M[3];
    const float M4 = M[4], M5 = M[5], M6  = M[6],  M7  = M[7];
    const float M8 = M[8], M9 = M[9], M10 = M[10], M11 = M[11];

    float4 dn = make_float4(0.f, 0.f, 0.f, 0.f);
    for (int j = row0 + q; j < row1; j += 16) {
        const int s = g_csr_src[j];
        const float4 as4 = *(const float4*)(g_as + s * 4);
        const float4 ea4 = ((const float4*)g_ea_csr)[j];
        float a0 = as4.x + ad4.x + ea4.x * M0  + ea4.y * M4 + ea4.z * M8;
        float a1 = as4.y + ad4.y + ea4.x * M1  + ea4.y * M5 + ea4.z * M9;
        float a2 = as4.z + ad4.z + ea4.x * M2_ + ea4.y * M6 + ea4.z * M10;
        float a3 = as4.w + ad4.w + ea4.x * M3  + ea4.y * M7 + ea4.z * M11;
        a0 = (a0 < 0.f) ? NEG_SLOPE * a0 : a0;
        a1 = (a1 < 0.f) ? NEG_SLOPE * a1 : a1;
        a2 = (a2 < 0.f) ? NEG_SLOPE * a2 : a2;
        a3 = (a3 < 0.f) ? NEG_SLOPE * a3 : a3;
        // softmax shift-invariance + alpha ~ O(10): segment-max pass skipped.
        const float4 ex = make_float4(__expf(a0), __expf(a1), __expf(a2), __expf(a3));
        ((float4*)g_exs)[j] = ex;
        dn.x += ex.x; dn.y += ex.y; dn.z += ex.z; dn.w += ex.w;
    }
#pragma unroll
    for (int o = 8; o; o >>= 1) {
        dn.x += __shfl_xor_sync(0xffffffffu, dn.x, o);
        dn.y += __shfl_xor_sync(0xffffffffu, dn.y, o);
        dn.z += __shfl_xor_sync(0xffffffffu, dn.z, o);
        dn.w += __shfl_xor_sync(0xffffffffu, dn.w, o);
    }
    const float i0 = __frcp_rn(dn.x + 1e-16f);
    const float i1 = __frcp_rn(dn.y + 1e-16f);
    const float i2 = __frcp_rn(dn.z + 1e-16f);
    const float i3 = __frcp_rn(dn.w + 1e-16f);
    __syncwarp();   // order g_exs stores before cross-lane readback

    float accA[8], accB[8];
#pragma unroll
    for (int i = 0; i < 8; i++) { accA[i] = 0.f; accB[i] = 0.f; }

    for (int j = row0; j < row1; j++) {
        const int s = g_csr_src[j];
        const float4 ex = ((const float4*)g_exs)[j];
        const float cA = (q < 8) ? (ex.x * i0) : (ex.y * i1);
        const float cB = (q < 8) ? (ex.z * i2) : (ex.w * i3);
        const __half* xr = g_xh + (size_t)s * HC;
        const uint4 hA = *(const uint4*)(xr + 8 * q);          // heads 0|1
        const uint4 hB = *(const uint4*)(xr + 128 + 8 * q);    // heads 2|3
        const float2 a0 = __half22float2(*(const __half2*)&hA.x);
        const float2 a1 = __half22float2(*(const __half2*)&hA.y);
        const float2 a2 = __half22float2(*(const __half2*)&hA.z);
        const float2 a3 = __half22float2(*(const __half2*)&hA.w);
        const float2 b0 = __half22float2(*(const __half2*)&hB.x);
        const float2 b1 = __half22float2(*(const __half2*)&hB.y);
        const float2 b2 = __half22float2(*(const __half2*)&hB.z);
        const float2 b3 = __half22float2(*(const __half2*)&hB.w);
        accA[0] = fmaf(cA, a0.x, accA[0]); accA[1] = fmaf(cA, a0.y, accA[1]);
        accA[2] = fmaf(cA, a1.x, accA[2]); accA[3] = fmaf(cA, a1.y, accA[3]);
        accA[4] = fmaf(cA, a2.x, accA[4]); accA[5] = fmaf(cA, a2.y, accA[5]);
        accA[6] = fmaf(cA, a3.x, accA[6]); accA[7] = fmaf(cA, a3.y, accA[7]);
        accB[0] = fmaf(cB, b0.x, accB[0]); accB[1] = fmaf(cB, b0.y, accB[1]);
        accB[2] = fmaf(cB, b1.x, accB[2]); accB[3] = fmaf(cB, b1.y, accB[3]);
        accB[4] = fmaf(cB, b2.x, accB[4]); accB[5] = fmaf(cB, b2.y, accB[5]);
        accB[6] = fmaf(cB, b3.x, accB[6]); accB[7] = fmaf(cB, b3.y, accB[7]);
    }

    float tot[8];
#pragma unroll
    for (int i = 0; i < 8; i++) {
        float v = accA[i] + accB[i];
        v += __shfl_xor_sync(0xffffffffu, v, 8);
        tot[i] = v;   // lane q now has full sum over 4 heads for c=8*(q&7)+i
    }

    const int c0i = 8 * (q & 7);
    float v[8];
    float s = 0.f;
#pragma unroll
    for (int i = 0; i < 8; i++) {
        v[i] = 0.25f * tot[i] + bias[c0i + i];
        s += v[i];
    }
#pragma unroll
    for (int o = 4; o; o >>= 1) s += __shfl_xor_sync(0xffffffffu, s, o);
    const float mu = s * (1.f / 64.f);
    float qs = 0.f;
#pragma unroll
    for (int i = 0; i < 8; i++) {
        v[i] -= mu;
        qs += v[i] * v[i];
    }
#pragma unroll
    for (int o = 4; o; o >>= 1) qs += __shfl_xor_sync(0xffffffffu, qs, o);
    const float rs = rsqrtf(qs * (1.f / 64.f) + LN_EPS);

    if (q < 8) {
        float y[8];
#pragma unroll
        for (int i = 0; i < 8; i++) {
            const float tv = v[i] * rs * gamma[c0i + i] + beta[c0i + i];
            y[i] = tv / (1.f + __expf(-tv));
        }
        if (layer == 0) {
            __half2* dst = (__half2*)(g_zh + (size_t)n * HID + c0i);
            dst[0] = __floats2half2_rn(y[0], y[1]);
            dst[1] = __floats2half2_rn(y[2], y[3]);
            dst[2] = __floats2half2_rn(y[4], y[5]);
            dst[3] = __floats2half2_rn(y[6], y[7]);
        } else {
            float4* dst = (float4*)(zout + (size_t)n * HID + c0i);
            dst[0] = make_float4(y[0], y[1], y[2], y[3]);
            dst[1] = make_float4(y[4], y[5], y[6], y[7]);
        }
    }
}

// ---------------- launcher ----------------
extern "C" void kernel_launch(void* const* d_in, const int* in_sizes, int n_in,
                              void* d_out, int out_size) {
    (void)in_sizes; (void)n_in; (void)out_size;
    const float* h     = (const float*)d_in[1];
    const void*  ei    = d_in[2];
    const float* ea    = (const float*)d_in[3];
    const float* W     = (const float*)d_in[4];
    const float* We    = (const float*)d_in[5];
    const float* as_   = (const float*)d_in[6];
    const float* ad_   = (const float*)d_in[7];
    const float* ae_   = (const float*)d_in[8];
    const float* bias  = (const float*)d_in[9];
    const float* gamma = (const float*)d_in[10];
    const float* beta  = (const float*)d_in[11];
    float* out = (float*)d_out;

    __half* wtp = nullptr;
    cudaGetSymbolAddress((void**)&wtp, g_wt);

    // ---- preamble: CSR build + fp16 conversions (all layer-invariant) ----
    k_detect_zero_M<<<(N_NODES + 255) / 256, 256>>>((const int*)ei, We, ae_);
    k_convert<<<(N_EDGES + 255) / 256, 256>>>(ei);
    k_h2h<<<(((N_NODES + N_PAD) * HID / 2) + 255) / 256, 256>>>(h);
    k_wt<<<(L_LAYERS * HC * HID + 255) / 256, 256>>>(W);
    k_scanA<<<N_SCAN_BLOCKS, SCAN_BLK>>>();
    k_scanB<<<1, 64>>>();
    k_scanC<<<N_SCAN_BLOCKS, SCAN_BLK>>>();
    k_fill<<<(N_EDGES + 255) / 256, 256>>>(ea);

    for (int l = 0; l < L_LAYERS; l++) {
        k_proj_mma<<<PROJ_BLOCKS, 256>>>(wtp + (size_t)l * HC * HID,
                                         as_ + (size_t)l * HC, ad_ + (size_t)l * HC);
        k_gat_msg<<<N_NODES / 16, 256>>>(l, out,
                                         bias + (size_t)l * HID,
                                         gamma + (size_t)l * HID,
                                         beta + (size_t)l * HID);
    }
}

// round 15
// speedup vs baseline: 1.5429x; 1.0099x over previous
#include <cuda_runtime.h>
#include <cuda_fp16.h>
#include <cstdint>

#define N_NODES 50000
#define N_EDGES 800000
#define HID 64
#define HEADS 4
#define CDIM 64
#define HC 256   // HEADS*CDIM
#define L_LAYERS 2
#define NEG_SLOPE 0.2f
#define LN_EPS 1e-5f
#define SCAN_BLK 1024
#define N_SCAN_BLOCKS ((N_NODES + SCAN_BLK - 1) / SCAN_BLK)   // 49
#define N_PAD 32
#define PROJ_BLOCKS ((N_NODES + 31) / 32)                     // 1563
#define E_PAD 8

// ---------------- device scratch (no allocations allowed) ----------------
__device__ __half g_xh[(size_t)N_NODES * HC];     // projected nodes, fp16 [N,256]
__device__ __half g_zh[(size_t)(N_NODES + N_PAD) * HID]; // activations, fp16 (padded)
__device__ __half g_wt[(size_t)L_LAYERS * HC * HID];     // W transposed fp16 [l][n][k]
__device__ float g_as[N_NODES * HEADS];           // alpha_src [N,4]
__device__ float g_ad[N_NODES * HEADS];           // alpha_dst [N,4]
__device__ float g_exs[(size_t)(N_EDGES + E_PAD) * HEADS]; // exp(alpha), CSR (padded)
__device__ float g_ea_csr[(size_t)N_EDGES * 4];   // edge_attr in CSR order [E,4]
__device__ int   g_src[N_EDGES];
__device__ int   g_dst[N_EDGES];
__device__ int   g_rank[N_EDGES];                 // rank of edge within its dst bucket
__device__ int   g_csr_src[N_EDGES + E_PAD];      // src id per CSR slot (padded)
__device__ int   g_rowptr[N_NODES + 1];           // raw per-block-scanned values
__device__ int   g_rowptr2[N_NODES + 1];          // finalized rowptr
__device__ int   g_deg[N_NODES];
__device__ int   g_bsum[N_SCAN_BLOCKS];
__device__ int   g_boff[N_SCAN_BLOCKS];
__device__ float g_M2[2 * 12];                    // edge-attr dual matrices, both layers
__device__ int   g_is64;

// ---------------- K0a: detect dtype + zero degrees + M (fused) ----------------
__global__ void k_detect_zero_M(const int* __restrict__ ei32,
                                const float* __restrict__ We,
                                const float* __restrict__ a_e) {
    const int i = blockIdx.x * blockDim.x + threadIdx.x;
    if (i < N_NODES) g_deg[i] = 0;
    if (i == 0) {
        int zeros = 0;
        for (int k = 1; k < 256; k += 2) if (ei32[k] == 0) zeros++;
        g_is64 = (zeros > 100) ? 1 : 0;   // int64 data: high words all zero
    }
    if (blockIdx.x == 0 && threadIdx.x >= 32 && threadIdx.x < 56) {
        const int t = threadIdx.x - 32;
        const int l = t / 12, r = t % 12;
        const int d = r >> 2, h = r & 3;
        const float* Wel = We + (size_t)l * 3 * HC;
        const float* ael = a_e + (size_t)l * HC;
        float s = 0.f;
        for (int c = 0; c < CDIM; c++)
            s += Wel[d * HC + h * CDIM + c] * ael[h * CDIM + c];
        g_M2[t] = s;   // layout g_M2[l*12 + d*4 + h]
    }
}

// ---------------- K0b: normalize edge index + count degrees + capture rank ----------------
__global__ void k_convert(const void* __restrict__ ei) {
    const int e = blockIdx.x * blockDim.x + threadIdx.x;
    if (e >= N_EDGES) return;
    int s, d;
    if (g_is64) {
        const long long* p = (const long long*)ei;
        s = (int)p[e]; d = (int)p[N_EDGES + e];
    } else {
        const int* p = (const int*)ei;
        s = p[e]; d = p[N_EDGES + e];
    }
    g_src[e] = s;
    g_dst[e] = d;
    g_rank[e] = atomicAdd(&g_deg[d], 1);
}

// ---------------- K0c: scan phase A — per-block exclusive scan ----------------
__global__ void __launch_bounds__(SCAN_BLK) k_scanA() {
    __shared__ int warp_sums[32];
    const int tid = threadIdx.x;
    const int i = blockIdx.x * SCAN_BLK + tid;
    const int v = (i < N_NODES) ? g_deg[i] : 0;
    int x = v;
#pragma unroll
    for (int o = 1; o < 32; o <<= 1) {
        int y = __shfl_up_sync(0xffffffffu, x, o);
        if ((tid & 31) >= o) x += y;
    }
    if ((tid & 31) == 31) warp_sums[tid >> 5] = x;
    __syncthreads();
    if (tid < 32) {
        int w = warp_sums[tid];
#pragma unroll
        for (int o = 1; o < 32; o <<= 1) {
            int y = __shfl_up_sync(0xffffffffu, w, o);
            if (tid >= o) w += y;
        }
        warp_sums[tid] = w;
    }
    __syncthreads();
    const int excl = x - v + ((tid >= 32) ? warp_sums[(tid >> 5) - 1] : 0);
    if (i < N_NODES) g_rowptr[i] = excl;
    if (tid == SCAN_BLK - 1) g_bsum[blockIdx.x] = excl + v;
}

// ---------------- K0d: scan phase B — scan the 49 block sums ----------------
__global__ void k_scanB() {
    __shared__ int s0;
    const int tid = threadIdx.x;   // 64 threads
    const int v = (tid < N_SCAN_BLOCKS) ? g_bsum[tid] : 0;
    int x = v;
#pragma unroll
    for (int o = 1; o < 32; o <<= 1) {
        int y = __shfl_up_sync(0xffffffffu, x, o);
        if ((tid & 31) >= o) x += y;
    }
    if (tid == 31) s0 = x;
    __syncthreads();
    if (tid >= 32) x += s0;
    if (tid < N_SCAN_BLOCKS) g_boff[tid] = x - v;
    if (tid == N_SCAN_BLOCKS - 1) g_rowptr2[N_NODES] = x;
}

// ---------------- K0e: fused finalize-rowptr + fill CSR (no atomics) ----------------
// Writes finalized rowptr to g_rowptr2 (separate array -> no race with the
// raw g_rowptr reads used for edge placement).
__global__ void k_scanC_fill(const float* __restrict__ ea) {
    const int i = blockIdx.x * blockDim.x + threadIdx.x;
    if (i < N_NODES)
        g_rowptr2[i] = g_rowptr[i] + g_boff[i >> 10];
    if (i < N_EDGES) {
        const int d = g_dst[i];
        const int pos = g_rowptr[d] + g_boff[d >> 10] + g_rank[i];
        g_csr_src[pos] = g_src[i];
        const float* p = ea + (size_t)i * 3;
        ((float4*)g_ea_csr)[pos] = make_float4(p[0], p[1], p[2], 0.f);
    }
}

// ---------------- K0f: convert h -> fp16 g_zh (with zero pad) ----------------
__global__ void k_h2h(const float* __restrict__ h) {
    const int i = blockIdx.x * blockDim.x + threadIdx.x;
    const int n_main = (N_NODES * HID) / 2;
    if (i < n_main) {
        const float2 v = ((const float2*)h)[i];
        ((__half2*)g_zh)[i] = __floats2half2_rn(v.x, v.y);
    } else if (i < n_main + (N_PAD * HID) / 2) {
        ((__half2*)g_zh)[i] = __floats2half2_rn(0.f, 0.f);
    }
}

// ---------------- K0g: transpose+convert W -> g_wt[l][n][k] fp16 ----------------
__global__ void k_wt(const float* __restrict__ W) {
    const int i = blockIdx.x * blockDim.x + threadIdx.x;   // over 2*256*64
    if (i >= L_LAYERS * HC * HID) return;
    const int l = i / (HC * HID);
    const int r = i % (HC * HID);
    const int n = r / HID;
    const int k = r % HID;
    g_wt[i] = __float2half(W[(size_t)l * HID * HC + (size_t)k * HC + n]);
}

// ---------------- K1: tensor-core node projection + alpha_src/alpha_dst ----------------
__global__ void __launch_bounds__(256) k_proj_mma(
    const __half* __restrict__ wt,    // this layer, [256][64]
    const float* __restrict__ a_s, const float* __restrict__ a_d)
{
    const int w = threadIdx.x >> 5;
    const int lane = threadIdx.x & 31;
    const int gid = lane >> 2;     // 0..7
    const int qd = lane & 3;       // quad index
    const int head = w & 3;
    const int n0 = blockIdx.x * 32 + (w >> 2) * 16;
    const int c0 = head * 64;

    const int r0 = n0 + gid;
    const __half* zrow0 = g_zh + (size_t)r0 * HID;
    const __half* zrow8 = g_zh + (size_t)(r0 + 8) * HID;

    float acc[8][4];
#pragma unroll
    for (int t = 0; t < 8; t++) { acc[t][0]=0.f; acc[t][1]=0.f; acc[t][2]=0.f; acc[t][3]=0.f; }

#pragma unroll
    for (int ks = 0; ks < 4; ks++) {
        const int k0 = ks * 16 + qd * 2;
        const uint32_t a0 = *(const uint32_t*)(zrow0 + k0);
        const uint32_t a1 = *(const uint32_t*)(zrow8 + k0);
        const uint32_t a2 = *(const uint32_t*)(zrow0 + k0 + 8);
        const uint32_t a3 = *(const uint32_t*)(zrow8 + k0 + 8);
#pragma unroll
        for (int t = 0; t < 8; t++) {
            const __half* wrow = wt + (size_t)(c0 + t * 8 + gid) * HID;
            const uint32_t b0 = *(const uint32_t*)(wrow + k0);
            const uint32_t b1 = *(const uint32_t*)(wrow + k0 + 8);
            asm volatile(
                "mma.sync.aligned.m16n8k16.row.col.f32.f16.f16.f32 "
                "{%0,%1,%2,%3}, {%4,%5,%6,%7}, {%8,%9}, {%0,%1,%2,%3};\n"
                : "+f"(acc[t][0]), "+f"(acc[t][1]), "+f"(acc[t][2]), "+f"(acc[t][3])
                : "r"(a0), "r"(a1), "r"(a2), "r"(a3), "r"(b0), "r"(b1));
        }
    }

    const bool ok0 = (r0 < N_NODES);
    const bool ok8 = (r0 + 8 < N_NODES);
    float as0 = 0.f, as8 = 0.f, ad0 = 0.f, ad8 = 0.f;
#pragma unroll
    for (int t = 0; t < 8; t++) {
        const int jc = c0 + t * 8 + qd * 2;
        if (ok0) *(__half2*)(g_xh + (size_t)r0 * HC + jc) = __floats2half2_rn(acc[t][0], acc[t][1]);
        if (ok8) *(__half2*)(g_xh + (size_t)(r0 + 8) * HC + jc) = __floats2half2_rn(acc[t][2], acc[t][3]);
        const float s0 = a_s[jc], s1 = a_s[jc + 1];
        const float d0 = a_d[jc], d1 = a_d[jc + 1];
        as0 += acc[t][0] * s0 + acc[t][1] * s1;
        as8 += acc[t][2] * s0 + acc[t][3] * s1;
        ad0 += acc[t][0] * d0 + acc[t][1] * d1;
        ad8 += acc[t][2] * d0 + acc[t][3] * d1;
    }
#pragma unroll
    for (int o = 1; o < 4; o <<= 1) {
        as0 += __shfl_xor_sync(0xffffffffu, as0, o);
        as8 += __shfl_xor_sync(0xffffffffu, as8, o);
        ad0 += __shfl_xor_sync(0xffffffffu, ad0, o);
        ad8 += __shfl_xor_sync(0xffffffffu, ad8, o);
    }
    if (qd == 0) {
        if (ok0) { g_as[r0 * 4 + head] = as0; g_ad[r0 * 4 + head] = ad0; }
        if (ok8) { g_as[(r0 + 8) * 4 + head] = as8; g_ad[(r0 + 8) * 4 + head] = ad8; }
    }
}

// ---------------- K2: fused alpha + CSR message pass + finalize ----------------
// 16 threads per dst node. Sweep-2 now software-pipelined WITHOUT branches:
// padded arrays make the j+1 prefetch unconditionally safe; only (s, ex)
// rotate as loop-carried values (small reg delta vs the failed R10/R11 forms).
__global__ void __launch_bounds__(256) k_gat_msg(
    int layer, float* __restrict__ zout, const float* __restrict__ bias,
    const float* __restrict__ gamma, const float* __restrict__ beta)
{
    const int t = threadIdx.x;
    const int q = t & 15;
    const int n = blockIdx.x * 16 + (t >> 4);
    const int row0 = g_rowptr2[n];
    const int row1 = g_rowptr2[n + 1];

    const float* M = g_M2 + layer * 12;
    const float4 ad4 = *(const float4*)(g_ad + n * 4);
    const float M0 = M[0], M1 = M[1], M2_ = M[2],  M3  = M[3];
    const float M4 = M[4], M5 = M[5], M6  = M[6],  M7  = M[7];
    const float M8 = M[8], M9 = M[9], M10 = M[10], M11 = M[11];

    // sweep 1: alpha -> exp per edge (lane-strided), denom accumulation,
    // coalesced store of ex into CSR order.
    float4 dn = make_float4(0.f, 0.f, 0.f, 0.f);
    for (int j = row0 + q; j < row1; j += 16) {
        const int s = g_csr_src[j];
        const float4 as4 = *(const float4*)(g_as + s * 4);
        const float4 ea4 = ((const float4*)g_ea_csr)[j];
        float a0 = as4.x + ad4.x + ea4.x * M0  + ea4.y * M4 + ea4.z * M8;
        float a1 = as4.y + ad4.y + ea4.x * M1  + ea4.y * M5 + ea4.z * M9;
        float a2 = as4.z + ad4.z + ea4.x * M2_ + ea4.y * M6 + ea4.z * M10;
        float a3 = as4.w + ad4.w + ea4.x * M3  + ea4.y * M7 + ea4.z * M11;
        a0 = (a0 < 0.f) ? NEG_SLOPE * a0 : a0;
        a1 = (a1 < 0.f) ? NEG_SLOPE * a1 : a1;
        a2 = (a2 < 0.f) ? NEG_SLOPE * a2 : a2;
        a3 = (a3 < 0.f) ? NEG_SLOPE * a3 : a3;
        // softmax shift-invariance + alpha ~ O(10): segment-max pass skipped.
        const float4 ex = make_float4(__expf(a0), __expf(a1), __expf(a2), __expf(a3));
        ((float4*)g_exs)[j] = ex;
        dn.x += ex.x; dn.y += ex.y; dn.z += ex.z; dn.w += ex.w;
    }
#pragma unroll
    for (int o = 8; o; o >>= 1) {
        dn.x += __shfl_xor_sync(0xffffffffu, dn.x, o);
        dn.y += __shfl_xor_sync(0xffffffffu, dn.y, o);
        dn.z += __shfl_xor_sync(0xffffffffu, dn.z, o);
        dn.w += __shfl_xor_sync(0xffffffffu, dn.w, o);
    }
    const float i0 = __frcp_rn(dn.x + 1e-16f);
    const float i1 = __frcp_rn(dn.y + 1e-16f);
    const float i2 = __frcp_rn(dn.z + 1e-16f);
    const float i3 = __frcp_rn(dn.w + 1e-16f);
    __syncwarp();   // order g_exs stores before cross-lane readback

    // sweep 2: serial edge walk with branch-free next-edge prefetch.
    float accA[8], accB[8];
#pragma unroll
    for (int i = 0; i < 8; i++) { accA[i] = 0.f; accB[i] = 0.f; }

    if (row0 < row1) {
        int s = g_csr_src[row0];
        float4 ex = ((const float4*)g_exs)[row0];
        for (int j = row0; j < row1; j++) {
            // unconditional prefetch of edge j+1 (padded arrays make it safe;
            // the final prefetch's values are rotated in but never used)
            const int sn = g_csr_src[j + 1];
            const float4 exn = ((const float4*)g_exs)[j + 1];

            const float cA = (q < 8) ? (ex.x * i0) : (ex.y * i1);
            const float cB = (q < 8) ? (ex.z * i2) : (ex.w * i3);
            const __half* xr = g_xh + (size_t)s * HC;
            const uint4 hA = *(const uint4*)(xr + 8 * q);          // heads 0|1
            const uint4 hB = *(const uint4*)(xr + 128 + 8 * q);    // heads 2|3
            const float2 a0 = __half22float2(*(const __half2*)&hA.x);
            const float2 a1 = __half22float2(*(const __half2*)&hA.y);
            const float2 a2 = __half22float2(*(const __half2*)&hA.z);
            const float2 a3 = __half22float2(*(const __half2*)&hA.w);
            const float2 b0 = __half22float2(*(const __half2*)&hB.x);
            const float2 b1 = __half22float2(*(const __half2*)&hB.y);
            const float2 b2 = __half22float2(*(const __half2*)&hB.z);
            const float2 b3 = __half22float2(*(const __half2*)&hB.w);
            accA[0] = fmaf(cA, a0.x, accA[0]); accA[1] = fmaf(cA, a0.y, accA[1]);
            accA[2] = fmaf(cA, a1.x, accA[2]); accA[3] = fmaf(cA, a1.y, accA[3]);
            accA[4] = fmaf(cA, a2.x, accA[4]); accA[5] = fmaf(cA, a2.y, accA[5]);
            accA[6] = fmaf(cA, a3.x, accA[6]); accA[7] = fmaf(cA, a3.y, accA[7]);
            accB[0] = fmaf(cB, b0.x, accB[0]); accB[1] = fmaf(cB, b0.y, accB[1]);
            accB[2] = fmaf(cB, b1.x, accB[2]); accB[3] = fmaf(cB, b1.y, accB[3]);
            accB[4] = fmaf(cB, b2.x, accB[4]); accB[5] = fmaf(cB, b2.y, accB[5]);
            accB[6] = fmaf(cB, b3.x, accB[6]); accB[7] = fmaf(cB, b3.y, accB[7]);

            s = sn; ex = exn;
        }
    }

    // combine the two head-halves across the 8-lane pairs
    float tot[8];
#pragma unroll
    for (int i = 0; i < 8; i++) {
        float v = accA[i] + accB[i];
        v += __shfl_xor_sync(0xffffffffu, v, 8);
        tot[i] = v;   // lane q now has full sum over 4 heads for c=8*(q&7)+i
    }

    // finalize: head-mean + bias + LN + SiLU (values mirrored in lane pairs)
    const int c0i = 8 * (q & 7);
    float v[8];
    float s = 0.f;
#pragma unroll
    for (int i = 0; i < 8; i++) {
        v[i] = 0.25f * tot[i] + bias[c0i + i];
        s += v[i];
    }
#pragma unroll
    for (int o = 4; o; o >>= 1) s += __shfl_xor_sync(0xffffffffu, s, o);
    const float mu = s * (1.f / 64.f);
    float qs = 0.f;
#pragma unroll
    for (int i = 0; i < 8; i++) {
        v[i] -= mu;
        qs += v[i] * v[i];
    }
#pragma unroll
    for (int o = 4; o; o >>= 1) qs += __shfl_xor_sync(0xffffffffu, qs, o);
    const float rs = rsqrtf(qs * (1.f / 64.f) + LN_EPS);

    if (q < 8) {
        float y[8];
#pragma unroll
        for (int i = 0; i < 8; i++) {
            const float tv = v[i] * rs * gamma[c0i + i] + beta[c0i + i];
            y[i] = tv / (1.f + __expf(-tv));
        }
        if (layer == 0) {
            __half2* dst = (__half2*)(g_zh + (size_t)n * HID + c0i);
            dst[0] = __floats2half2_rn(y[0], y[1]);
            dst[1] = __floats2half2_rn(y[2], y[3]);
            dst[2] = __floats2half2_rn(y[4], y[5]);
            dst[3] = __floats2half2_rn(y[6], y[7]);
        } else {
            float4* dst = (float4*)(zout + (size_t)n * HID + c0i);
            dst[0] = make_float4(y[0], y[1], y[2], y[3]);
            dst[1] = make_float4(y[4], y[5], y[6], y[7]);
        }
    }
}

// ---------------- launcher ----------------
extern "C" void kernel_launch(void* const* d_in, const int* in_sizes, int n_in,
                              void* d_out, int out_size) {
    (void)in_sizes; (void)n_in; (void)out_size;
    const float* h     = (const float*)d_in[1];
    const void*  ei    = d_in[2];
    const float* ea    = (const float*)d_in[3];
    const float* W     = (const float*)d_in[4];
    const float* We    = (const float*)d_in[5];
    const float* as_   = (const float*)d_in[6];
    const float* ad_   = (const float*)d_in[7];
    const float* ae_   = (const float*)d_in[8];
    const float* bias  = (const float*)d_in[9];
    const float* gamma = (const float*)d_in[10];
    const float* beta  = (const float*)d_in[11];
    float* out = (float*)d_out;

    __half* wtp = nullptr;
    cudaGetSymbolAddress((void**)&wtp, g_wt);

    // ---- preamble: CSR build + fp16 conversions (all layer-invariant) ----
    k_detect_zero_M<<<(N_NODES + 255) / 256, 256>>>((const int*)ei, We, ae_);
    k_convert<<<(N_EDGES + 255) / 256, 256>>>(ei);
    k_h2h<<<(((N_NODES + N_PAD) * HID / 2) + 255) / 256, 256>>>(h);
    k_wt<<<(L_LAYERS * HC * HID + 255) / 256, 256>>>(W);
    k_scanA<<<N_SCAN_BLOCKS, SCAN_BLK>>>();
    k_scanB<<<1, 64>>>();
    k_scanC_fill<<<(N_EDGES + 255) / 256, 256>>>(ea);

    for (int l = 0; l < L_LAYERS; l++) {
        k_proj_mma<<<PROJ_BLOCKS, 256>>>(wtp + (size_t)l * HC * HID,
                                         as_ + (size_t)l * HC, ad_ + (size_t)l * HC);
        k_gat_msg<<<N_NODES / 16, 256>>>(l, out,
                                         bias + (size_t)l * HID,
                                         gamma + (size_t)l * HID,
                                         beta + (size_t)l * HID);
    }
}